// round 12
// baseline (speedup 1.0000x reference)
#include <cuda_runtime.h>
#include <cuda_bf16.h>
#include <cstdint>
#include <math.h>

#define Bb 4
#define Ll 4096
#define Dd 512
#define Hh 8
#define DK 64
#define Uu 45
#define SCALE 0.125f
#define MM 16384
#define MK 8388608
#define WSZ 262144

// ---------------- PTX helpers (plain-sm_103-legal) ---------------------------
__device__ __forceinline__ uint32_t smem_u32(const void* p) {
    uint32_t a;
    asm("{ .reg .u64 t; cvta.to.shared.u64 t, %1; cvt.u32.u64 %0, t; }" : "=r"(a) : "l"(p));
    return a;
}
#define CP_ASYNC16(dst, src) \
    asm volatile("cp.async.cg.shared.global [%0], [%1], 16;" :: "r"(dst), "l"(src))
#define CP_COMMIT() asm volatile("cp.async.commit_group;" ::: "memory")
#define CP_WAIT1()  asm volatile("cp.async.wait_group 1;" ::: "memory")
#define CP_WAIT0()  asm volatile("cp.async.wait_group 0;" ::: "memory")

__device__ __forceinline__ void ldsm_x4(uint32_t* r, uint32_t addr) {
    asm volatile("ldmatrix.sync.aligned.m8n8.x4.shared.b16 {%0,%1,%2,%3}, [%4];"
        : "=r"(r[0]), "=r"(r[1]), "=r"(r[2]), "=r"(r[3]) : "r"(addr));
}
__device__ __forceinline__ void mma_bf16(float* d, const uint32_t* a, uint32_t b0, uint32_t b1) {
    asm volatile("mma.sync.aligned.m16n8k16.row.col.f32.bf16.bf16.f32 "
        "{%0,%1,%2,%3}, {%4,%5,%6,%7}, {%8,%9}, {%0,%1,%2,%3};"
        : "+f"(d[0]), "+f"(d[1]), "+f"(d[2]), "+f"(d[3])
        : "r"(a[0]), "r"(a[1]), "r"(a[2]), "r"(a[3]), "r"(b0), "r"(b1));
}

// ---------------- scratch ----------------------------------------------------
__device__ __nv_bfloat16 g_XH[3 * MK];
__device__ __nv_bfloat16 g_XL[3 * MK];
__device__ __nv_bfloat16 g_X2[3 * MK];
__device__ __nv_bfloat16 g_WtH[4 * WSZ];
__device__ __nv_bfloat16 g_WtL[4 * WSZ];
__device__ __nv_bfloat16 g_Wt2[4 * WSZ];
__device__ float g_P[3 * MK];              // Qp | Kp | Vp, (B,L,H,dk)
__device__ __nv_bfloat16 g_ctxH[MK];
__device__ __nv_bfloat16 g_ctxL[MK];
__device__ float g_M[Bb * Hh * Ll];
__device__ float g_vpart[Bb * 32 * Dd];
__device__ float g_vmean[Bb * Dd];
__device__ int   g_top[Bb * Hh * Uu];
__device__ float g_part[32 * 32 * Uu * DK];   // [bh][chunk][u][d]

// ---------------- 3-level split, all inputs in one launch --------------------
__global__ __launch_bounds__(256) void conv_split3_all(
    const float* __restrict__ q, const float* __restrict__ k, const float* __restrict__ v,
    __nv_bfloat16* __restrict__ H, __nv_bfloat16* __restrict__ L,
    __nv_bfloat16* __restrict__ X2)
{
    int z = blockIdx.z;
    int i = blockIdx.x * 256 + threadIdx.x;
    const float* src = (z == 0) ? q : (z == 1) ? k : v;
    float4 val = ((const float4*)src)[i];
    size_t o = (size_t)z * (MK / 4) + i;
    float vv[4] = {val.x, val.y, val.z, val.w};
    __nv_bfloat16 hh[4], mm[4], ll[4];
#pragma unroll
    for (int j = 0; j < 4; j++) {
        hh[j] = __float2bfloat16(vv[j]);
        float r1 = vv[j] - __bfloat162float(hh[j]);
        mm[j] = __float2bfloat16(r1);
        ll[j] = __float2bfloat16(r1 - __bfloat162float(mm[j]));
    }
    ((__nv_bfloat162*)H)[2 * o + 0] = __halves2bfloat162(hh[0], hh[1]);
    ((__nv_bfloat162*)H)[2 * o + 1] = __halves2bfloat162(hh[2], hh[3]);
    ((__nv_bfloat162*)L)[2 * o + 0] = __halves2bfloat162(mm[0], mm[1]);
    ((__nv_bfloat162*)L)[2 * o + 1] = __halves2bfloat162(mm[2], mm[3]);
    if (z < 2) {
        ((__nv_bfloat162*)X2)[2 * o + 0] = __halves2bfloat162(ll[0], ll[1]);
        ((__nv_bfloat162*)X2)[2 * o + 1] = __halves2bfloat162(ll[2], ll[3]);
    }
}

// ---------------- weight transpose + 3-level split ---------------------------
__global__ void conv_w3_all(const float* __restrict__ Wq, const float* __restrict__ Wk,
                            const float* __restrict__ Wv, const float* __restrict__ Wo,
                            __nv_bfloat16* __restrict__ WtH,
                            __nv_bfloat16* __restrict__ WtL,
                            __nv_bfloat16* __restrict__ Wt2)
{
    __shared__ float t[32][33];
    int z = blockIdx.z;
    const float* W = (z == 0) ? Wq : (z == 1) ? Wk : (z == 2) ? Wv : Wo;
    size_t base = (size_t)z * WSZ;
    int n0 = blockIdx.x * 32, k0 = blockIdx.y * 32;
    int tx = threadIdx.x, ty = threadIdx.y;
#pragma unroll
    for (int i = 0; i < 4; i++)
        t[ty + i * 8][tx] = W[(size_t)(k0 + ty + i * 8) * 512 + n0 + tx];
    __syncthreads();
#pragma unroll
    for (int i = 0; i < 4; i++) {
        int n = n0 + ty + i * 8;
        float v = t[tx][ty + i * 8];
        __nv_bfloat16 hb = __float2bfloat16(v);
        float r1 = v - __bfloat162float(hb);
        __nv_bfloat16 mb = __float2bfloat16(r1);
        WtH[base + (size_t)n * 512 + k0 + tx] = hb;
        WtL[base + (size_t)n * 512 + k0 + tx] = mb;
        Wt2[base + (size_t)n * 512 + k0 + tx] = __float2bfloat16(r1 - __bfloat162float(mb));
    }
}

// ---------------- shared GEMM constants --------------------------------------
__device__ __constant__ int c_tA[6] = {0, 0, 1, 0, 2, 1};
__device__ __constant__ int c_tB[6] = {0, 1, 0, 2, 0, 1};
#define LDAB 40
#define STG_BYTES (128 * LDAB * 2)          // 10240 per tile
#define GEMM_SMEM (3 * 2 * STG_BYTES)       // pairwise kernel: 61440
#define STG6 (6 * STG_BYTES)                // grouped stage: 61440
#define QK6_SMEM (3 * STG6)                 // 184320

// ---------------- grouped 6-term Q/K GEMM (1 sync per 32-K chunk) ------------
__global__ __launch_bounds__(256) void gemm_qk6(
    const __nv_bfloat16* __restrict__ XH, const __nv_bfloat16* __restrict__ XL,
    const __nv_bfloat16* __restrict__ X2,
    const __nv_bfloat16* __restrict__ WtH, const __nv_bfloat16* __restrict__ WtL,
    const __nv_bfloat16* __restrict__ Wt2,
    const float* __restrict__ bq, const float* __restrict__ bk,
    float* __restrict__ P)
{
    extern __shared__ char sm[];
    const int tid = threadIdx.x;
    const int w = tid >> 5, lane = tid & 31;
    const int z = blockIdx.z;                    // 0=Q, 1=K
    const int m0 = blockIdx.x * 128, n0 = blockIdx.y * 128;
    const int NCH = 16;

    const __nv_bfloat16* Alev[3] = {XH + (size_t)z * MK, XL + (size_t)z * MK, X2 + (size_t)z * MK};
    const __nv_bfloat16* Blev[3] = {WtH + (size_t)z * WSZ, WtL + (size_t)z * WSZ, Wt2 + (size_t)z * WSZ};

    const int m_off = (w >> 2) * 64, n_off = (w & 3) * 32;
    const int mi = lane >> 3, r8 = lane & 7;

    float acc[4][4][4];
#pragma unroll
    for (int i = 0; i < 4; i++)
#pragma unroll
        for (int j = 0; j < 4; j++)
#pragma unroll
            for (int q = 0; q < 4; q++) acc[i][j][q] = 0.f;

    const uint32_t sbase = smem_u32(sm);
    const int lrow = tid >> 2;
    const int lcg  = (tid & 3) * 8;

    auto load_chunk = [&](int c, int stg) {
        int k0 = c * 32;
        uint32_t sb = sbase + stg * STG6;
#pragma unroll
        for (int t = 0; t < 3; t++) {
            const __nv_bfloat16* src = Alev[t];
#pragma unroll
            for (int i = 0; i < 2; i++) {
                int row = lrow + i * 64;
                CP_ASYNC16(sb + t * STG_BYTES + (row * LDAB + lcg) * 2,
                           src + (size_t)(m0 + row) * 512 + k0 + lcg);
            }
        }
#pragma unroll
        for (int t = 0; t < 3; t++) {
            const __nv_bfloat16* src = Blev[t];
#pragma unroll
            for (int i = 0; i < 2; i++) {
                int row = lrow + i * 64;
                CP_ASYNC16(sb + (3 + t) * STG_BYTES + (row * LDAB + lcg) * 2,
                           src + (size_t)(n0 + row) * 512 + k0 + lcg);
            }
        }
    };

    load_chunk(0, 0); CP_COMMIT();
    load_chunk(1, 1); CP_COMMIT();

    int buf = 0, pre = 2;
    for (int c = 0; c < NCH; c++) {
        CP_WAIT1();
        __syncthreads();
        if (c + 2 < NCH) load_chunk(c + 2, pre);
        CP_COMMIT();

        uint32_t sb = sbase + buf * STG6;
#pragma unroll
        for (int kk = 0; kk < 2; kk++) {
            uint32_t a[3][4][4], b[3][2][4];
#pragma unroll
            for (int lev = 0; lev < 3; lev++)
#pragma unroll
                for (int i = 0; i < 4; i++)
                    ldsm_x4(a[lev][i], sb + lev * STG_BYTES
                            + (uint32_t)(m_off + i * 16 + ((mi & 1) << 3) + r8) * 80
                            + kk * 32 + ((mi >> 1) << 4));
#pragma unroll
            for (int lev = 0; lev < 3; lev++)
#pragma unroll
                for (int jg = 0; jg < 2; jg++)
                    ldsm_x4(b[lev][jg], sb + (3 + lev) * STG_BYTES
                            + (uint32_t)(n_off + jg * 16 + ((mi >> 1) << 3) + r8) * 80
                            + kk * 32 + ((mi & 1) << 4));
#pragma unroll
            for (int t = 0; t < 6; t++) {
                int al = c_tA[t], bl = c_tB[t];
#pragma unroll
                for (int i = 0; i < 4; i++)
#pragma unroll
                    for (int j = 0; j < 4; j++)
                        mma_bf16(acc[i][j], a[al][i],
                                 b[bl][j >> 1][(j & 1) * 2], b[bl][j >> 1][(j & 1) * 2 + 1]);
            }
        }
        buf = (buf == 2) ? 0 : buf + 1;
        pre = (pre == 2) ? 0 : pre + 1;
    }

    const float* bs = (z == 0) ? bq : bk;
    float* Cz = P + (size_t)z * MK;
#pragma unroll
    for (int i = 0; i < 4; i++) {
        int row0 = m0 + m_off + i * 16 + (lane >> 2);
#pragma unroll
        for (int j = 0; j < 4; j++) {
            int col = n0 + n_off + j * 8 + (lane & 3) * 2;
            float bx = bs[col], by = bs[col + 1];
            float2 v0 = make_float2(acc[i][j][0] + bx, acc[i][j][1] + by);
            float2 v1 = make_float2(acc[i][j][2] + bx, acc[i][j][3] + by);
            *(float2*)(Cz + (size_t)row0 * 512 + col) = v0;
            *(float2*)(Cz + (size_t)(row0 + 8) * 512 + col) = v1;
        }
    }
}

// ---------------- pairwise HMMA GEMM (verified; used for V via zbase) --------
__global__ __launch_bounds__(256, 2) void gemm_hmma(
    const __nv_bfloat16* __restrict__ A0, const __nv_bfloat16* __restrict__ A1,
    const __nv_bfloat16* __restrict__ A2,
    const __nv_bfloat16* __restrict__ B0, const __nv_bfloat16* __restrict__ B1,
    const __nv_bfloat16* __restrict__ B2,
    const float* __restrict__ bi0, const float* __restrict__ bi1, const float* __restrict__ bi2,
    float* __restrict__ Cout, int zbase)
{
    extern __shared__ char sm[];
    const int tid = threadIdx.x;
    const int w = tid >> 5, lane = tid & 31;
    const int z = blockIdx.z + zbase;
    const int m0 = blockIdx.x * 128, n0 = blockIdx.y * 128;
    const int nt = (z == 2) ? 3 : 6;
    const int NCH = nt * 16;

    const __nv_bfloat16* Alev[3] = {A0 + (size_t)z * MK, A1 + (size_t)z * MK, A2 + (size_t)z * MK};
    const __nv_bfloat16* Blev[3] = {B0 + (size_t)z * WSZ, B1 + (size_t)z * WSZ, B2 + (size_t)z * WSZ};

    const int m_off = (w >> 2) * 64, n_off = (w & 3) * 32;
    const int mi = lane >> 3, r8 = lane & 7;

    float acc[4][4][4];
#pragma unroll
    for (int i = 0; i < 4; i++)
#pragma unroll
        for (int j = 0; j < 4; j++)
#pragma unroll
            for (int q = 0; q < 4; q++) acc[i][j][q] = 0.f;

    const uint32_t sbase = smem_u32(sm);
    const int lrow = tid >> 2;
    const int lcg  = (tid & 3) * 8;

    auto load_chunk = [&](int c, int stg) {
        int t = c >> 4, k0 = (c & 15) * 32;
        const __nv_bfloat16* Asrc = Alev[c_tA[t]];
        const __nv_bfloat16* Bsrc = Blev[c_tB[t]];
        uint32_t sA = sbase + stg * (2 * STG_BYTES);
        uint32_t sB = sA + STG_BYTES;
#pragma unroll
        for (int i = 0; i < 2; i++) {
            int row = lrow + i * 64;
            CP_ASYNC16(sA + (row * LDAB + lcg) * 2, Asrc + (size_t)(m0 + row) * 512 + k0 + lcg);
            CP_ASYNC16(sB + (row * LDAB + lcg) * 2, Bsrc + (size_t)(n0 + row) * 512 + k0 + lcg);
        }
    };

    load_chunk(0, 0); CP_COMMIT();
    load_chunk(1, 1); CP_COMMIT();

    int buf = 0, pre = 2;
    for (int c = 0; c < NCH; c++) {
        CP_WAIT1();
        __syncthreads();
        if (c + 2 < NCH) load_chunk(c + 2, pre);
        CP_COMMIT();

        uint32_t sA = sbase + buf * (2 * STG_BYTES);
        uint32_t sB = sA + STG_BYTES;
#pragma unroll
        for (int kk = 0; kk < 2; kk++) {
            uint32_t a[4][4], b[2][4];
#pragma unroll
            for (int i = 0; i < 4; i++)
                ldsm_x4(a[i], sA + (uint32_t)(m_off + i * 16 + ((mi & 1) << 3) + r8) * 80
                              + kk * 32 + ((mi >> 1) << 4));
#pragma unroll
            for (int jg = 0; jg < 2; jg++)
                ldsm_x4(b[jg], sB + (uint32_t)(n_off + jg * 16 + ((mi >> 1) << 3) + r8) * 80
                               + kk * 32 + ((mi & 1) << 4));
#pragma unroll
            for (int i = 0; i < 4; i++)
#pragma unroll
                for (int j = 0; j < 4; j++)
                    mma_bf16(acc[i][j], a[i], b[j >> 1][(j & 1) * 2], b[j >> 1][(j & 1) * 2 + 1]);
        }
        buf = (buf == 2) ? 0 : buf + 1;
        pre = (pre == 2) ? 0 : pre + 1;
    }

    const float* bs = (z == 0) ? bi0 : (z == 1) ? bi1 : bi2;
    float* Cz = Cout + (size_t)z * MK;
#pragma unroll
    for (int i = 0; i < 4; i++) {
        int row0 = m0 + m_off + i * 16 + (lane >> 2);
#pragma unroll
        for (int j = 0; j < 4; j++) {
            int col = n0 + n_off + j * 8 + (lane & 3) * 2;
            float bx = bs[col], by = bs[col + 1];
            float2 v0 = make_float2(acc[i][j][0] + bx, acc[i][j][1] + by);
            float2 v1 = make_float2(acc[i][j][2] + bx, acc[i][j][3] + by);
            *(float2*)(Cz + (size_t)row0 * 512 + col) = v0;
            *(float2*)(Cz + (size_t)(row0 + 8) * 512 + col) = v1;
        }
    }
}

// ---------------- output GEMM: bf16 A (ctxH/ctxL), 3 terms --------------------
__global__ __launch_bounds__(256, 2) void gemm_out(
    const __nv_bfloat16* __restrict__ A0, const __nv_bfloat16* __restrict__ A1,
    const __nv_bfloat16* __restrict__ B0, const __nv_bfloat16* __restrict__ B1,
    const float* __restrict__ bias, float* __restrict__ Cout)
{
    extern __shared__ char sm[];
    const int tid = threadIdx.x;
    const int w = tid >> 5, lane = tid & 31;
    const int m0 = blockIdx.x * 128, n0 = blockIdx.y * 128;
    const int NCH = 48;

    const __nv_bfloat16* Alev[2] = {A0, A1};
    const __nv_bfloat16* Blev[2] = {B0, B1};

    const int m_off = (w >> 2) * 64, n_off = (w & 3) * 32;
    const int mi = lane >> 3, r8 = lane & 7;

    float acc[4][4][4];
#pragma unroll
    for (int i = 0; i < 4; i++)
#pragma unroll
        for (int j = 0; j < 4; j++)
#pragma unroll
            for (int q = 0; q < 4; q++) acc[i][j][q] = 0.f;

    const uint32_t sbase = smem_u32(sm);
    const int lrow = tid >> 2;
    const int lcg  = (tid & 3) * 8;

    auto load_chunk = [&](int c, int stg) {
        int t = c >> 4, k0 = (c & 15) * 32;
        const __nv_bfloat16* As = Alev[c_tA[t]];
        const __nv_bfloat16* Bs = Blev[c_tB[t]];
        uint32_t sA = sbase + stg * (2 * STG_BYTES);
        uint32_t sB = sA + STG_BYTES;
#pragma unroll
        for (int i = 0; i < 2; i++) {
            int row = lrow + i * 64;
            CP_ASYNC16(sA + (row * LDAB + lcg) * 2, As + (size_t)(m0 + row) * 512 + k0 + lcg);
            CP_ASYNC16(sB + (row * LDAB + lcg) * 2, Bs + (size_t)(n0 + row) * 512 + k0 + lcg);
        }
    };

    load_chunk(0, 0); CP_COMMIT();
    load_chunk(1, 1); CP_COMMIT();

    int buf = 0, pre = 2;
    for (int c = 0; c < NCH; c++) {
        CP_WAIT1();
        __syncthreads();
        if (c + 2 < NCH) load_chunk(c + 2, pre);
        CP_COMMIT();

        uint32_t sA = sbase + buf * (2 * STG_BYTES);
        uint32_t sB = sA + STG_BYTES;
#pragma unroll
        for (int kk = 0; kk < 2; kk++) {
            uint32_t a[4][4], b[2][4];
#pragma unroll
            for (int i = 0; i < 4; i++)
                ldsm_x4(a[i], sA + (uint32_t)(m_off + i * 16 + ((mi & 1) << 3) + r8) * 80
                              + kk * 32 + ((mi >> 1) << 4));
#pragma unroll
            for (int jg = 0; jg < 2; jg++)
                ldsm_x4(b[jg], sB + (uint32_t)(n_off + jg * 16 + ((mi >> 1) << 3) + r8) * 80
                               + kk * 32 + ((mi & 1) << 4));
#pragma unroll
            for (int i = 0; i < 4; i++)
#pragma unroll
                for (int j = 0; j < 4; j++)
                    mma_bf16(acc[i][j], a[i], b[j >> 1][(j & 1) * 2], b[j >> 1][(j & 1) * 2 + 1]);
        }
        buf = (buf == 2) ? 0 : buf + 1;
        pre = (pre == 2) ? 0 : pre + 1;
    }

#pragma unroll
    for (int i = 0; i < 4; i++) {
        int row0 = m0 + m_off + i * 16 + (lane >> 2);
#pragma unroll
        for (int j = 0; j < 4; j++) {
            int col = n0 + n_off + j * 8 + (lane & 3) * 2;
            float bx = bias[col], by = bias[col + 1];
            float2 v0 = make_float2(acc[i][j][0] + bx, acc[i][j][1] + by);
            float2 v1 = make_float2(acc[i][j][2] + bx, acc[i][j][3] + by);
            *(float2*)(Cout + (size_t)row0 * 512 + col) = v0;
            *(float2*)(Cout + (size_t)(row0 + 8) * 512 + col) = v1;
        }
    }
}

// ---------------- V mean: coalesced two-stage --------------------------------
__global__ __launch_bounds__(256) void vmean1(const float* __restrict__ Vp, float* __restrict__ vpart)
{
    int b = blockIdx.x, c = blockIdx.y;
    int col4 = threadIdx.x & 127;
    int half = threadIdx.x >> 7;
    const float4* base = (const float4*)(Vp + (size_t)(b * Ll + c * 128) * Dd);
    float4 acc = make_float4(0.f, 0.f, 0.f, 0.f);
    for (int r = half; r < 128; r += 2) {
        float4 v = base[(size_t)r * 128 + col4];
        acc.x += v.x; acc.y += v.y; acc.z += v.z; acc.w += v.w;
    }
    __shared__ float4 smv[128];
    if (half == 1) smv[col4] = acc;
    __syncthreads();
    if (half == 0) {
        float4 o = smv[col4];
        o.x += acc.x; o.y += acc.y; o.z += acc.z; o.w += acc.w;
        ((float4*)vpart)[((size_t)(b * 32 + c)) * 128 + col4] = o;
    }
}

__global__ void vmean2(const float* __restrict__ vpart, float* __restrict__ vmean)
{
    int b = blockIdx.x, d = threadIdx.x;
    float s = 0.f;
    for (int c = 0; c < 32; c++) s += vpart[((size_t)(b * 32 + c)) * 512 + d];
    vmean[b * Dd + d] = s * (1.0f / Ll);
}

// ---------------- ctx broadcast directly into bf16 levels --------------------
__global__ __launch_bounds__(256) void fill_ctx2(const float* __restrict__ vmean,
                                                 __nv_bfloat16* __restrict__ ctxH,
                                                 __nv_bfloat16* __restrict__ ctxL)
{
    int i = blockIdx.x * 256 + threadIdx.x;
    int b4 = i / (Ll * Dd / 4);
    int c4 = i % (Dd / 4);
    float4 v = ((const float4*)vmean)[b4 * (Dd / 4) + c4];
    float f[4] = {v.x, v.y, v.z, v.w};
    __nv_bfloat16 h[4], l[4];
#pragma unroll
    for (int j = 0; j < 4; j++) {
        h[j] = __float2bfloat16(f[j]);
        l[j] = __float2bfloat16(f[j] - __bfloat162float(h[j]));
    }
    ((__nv_bfloat162*)ctxH)[2 * i + 0] = __halves2bfloat162(h[0], h[1]);
    ((__nv_bfloat162*)ctxH)[2 * i + 1] = __halves2bfloat162(h[2], h[3]);
    ((__nv_bfloat162*)ctxL)[2 * i + 0] = __halves2bfloat162(l[0], l[1]);
    ((__nv_bfloat162*)ctxL)[2 * i + 1] = __halves2bfloat162(l[2], l[3]);
}

// ---------------- sparse metric (d-tiled) ------------------------------------
__global__ __launch_bounds__(256) void metric_kernel(const float* __restrict__ Qp,
                                                     const float* __restrict__ Kp,
                                                     const int* __restrict__ sample_idx,
                                                     float* __restrict__ Mout)
{
    int b = blockIdx.z, h = blockIdx.y;
    int l = blockIdx.x * 256 + threadIdx.x;
    __shared__ float Ks[Uu * DK];
    for (int i = threadIdx.x; i < Uu * DK; i += 256) {
        int j = i / DK, d = i % DK;
        int ksl = sample_idx[j];
        Ks[i] = Kp[((size_t)(b * Ll + ksl) * Hh + h) * DK + d];
    }
    __syncthreads();
    const float* qp = &Qp[((size_t)(b * Ll + l) * Hh + h) * DK];
    float acc[Uu];
#pragma unroll
    for (int u = 0; u < Uu; u++) acc[u] = 0.f;
    for (int d0 = 0; d0 < DK; d0 += 8) {
        float4 a0 = *(const float4*)(qp + d0);
        float4 a1 = *(const float4*)(qp + d0 + 4);
#pragma unroll
        for (int u = 0; u < Uu; u++) {
            float4 b0 = *(const float4*)&Ks[u * DK + d0];
            float4 b1 = *(const float4*)&Ks[u * DK + d0 + 4];
            acc[u] += a0.x * b0.x + a0.y * b0.y + a0.z * b0.z + a0.w * b0.w
                    + a1.x * b1.x + a1.y * b1.y + a1.z * b1.z + a1.w * b1.w;
        }
    }
    float mx = -1e30f, sum = 0.f;
#pragma unroll
    for (int u = 0; u < Uu; u++) { mx = fmaxf(mx, acc[u]); sum += acc[u]; }
    Mout[(b * Hh + h) * Ll + l] = mx - sum * (1.0f / Uu);
}

// ---------------- top-45: register-resident + warp shuffles -------------------
__global__ __launch_bounds__(1024) void topk_kernel(const float* __restrict__ Min, int* __restrict__ top)
{
    int bh = blockIdx.x;
    int tid = threadIdx.x;
    int lane = tid & 31, wrp = tid >> 5;
    float4 vv = ((const float4*)(Min + (size_t)bh * Ll))[tid];
    float v[4] = {vv.x, vv.y, vv.z, vv.w};
    __shared__ float swv[32];
    __shared__ int   swi[32];
    __shared__ int   sbwi;

    for (int it = 0; it < Uu; it++) {
        float bv = v[0]; int bj = 0;
#pragma unroll
        for (int j = 1; j < 4; j++) if (v[j] > bv) { bv = v[j]; bj = j; }
        int bi = tid * 4 + bj;
#pragma unroll
        for (int s = 16; s > 0; s >>= 1) {
            float ov = __shfl_down_sync(0xffffffffu, bv, s);
            int   oi = __shfl_down_sync(0xffffffffu, bi, s);
            if (ov > bv || (ov == bv && oi < bi)) { bv = ov; bi = oi; }
        }
        if (lane == 0) { swv[wrp] = bv; swi[wrp] = bi; }
        __syncthreads();
        if (wrp == 0) {
            bv = swv[lane]; bi = swi[lane];
#pragma unroll
            for (int s = 16; s > 0; s >>= 1) {
                float ov = __shfl_down_sync(0xffffffffu, bv, s);
                int   oi = __shfl_down_sync(0xffffffffu, bi, s);
                if (ov > bv || (ov == bv && oi < bi)) { bv = ov; bi = oi; }
            }
            if (lane == 0) { sbwi = bi; top[bh * Uu + it] = bi; }
        }
        __syncthreads();
        int widx = sbwi;
        if ((widx >> 2) == tid) v[widx & 3] = -1e38f;
    }
}

// ---------------- attention pass 1: raw scaled scores -------------------------
__global__ __launch_bounds__(256) void attn_scores(const float* __restrict__ Qp,
                                                   const float* __restrict__ Kp,
                                                   const int* __restrict__ top,
                                                   float* __restrict__ attn)
{
    int kc = blockIdx.x, h = blockIdx.y, b = blockIdx.z;
    int bh = b * Hh + h;
    __shared__ float Qs[Uu * DK];
    for (int i = threadIdx.x; i < Uu * DK; i += 256) {
        int u = i >> 6, d = i & 63;
        int lsel = top[bh * Uu + u];
        Qs[i] = Qp[((size_t)(b * Ll + lsel) * Hh + h) * DK + d];
    }
    __syncthreads();
    int k = kc * 256 + threadIdx.x;
    const float* kp = Kp + ((size_t)(b * Ll + k) * Hh + h) * DK;
    float acc[Uu];
#pragma unroll
    for (int u = 0; u < Uu; u++) acc[u] = 0.f;
    for (int d0 = 0; d0 < DK; d0 += 8) {
        float4 k0 = *(const float4*)(kp + d0);
        float4 k1 = *(const float4*)(kp + d0 + 4);
#pragma unroll
        for (int u = 0; u < Uu; u++) {
            float4 q0 = *(const float4*)&Qs[u * DK + d0];
            float4 q1 = *(const float4*)&Qs[u * DK + d0 + 4];
            acc[u] += k0.x * q0.x + k0.y * q0.y + k0.z * q0.z + k0.w * q0.w
                    + k1.x * q1.x + k1.y * q1.y + k1.z * q1.z + k1.w * q1.w;
        }
    }
    float* ap = attn + (size_t)bh * Uu * Ll + k;
#pragma unroll
    for (int u = 0; u < Uu; u++) ap[(size_t)u * Ll] = acc[u] * SCALE;
}

// ---------------- attention pass 2: softmax in place --------------------------
__global__ __launch_bounds__(256) void attn_softmax(float* __restrict__ attn)
{
    size_t row = blockIdx.x;
    float* ap = attn + row * Ll;
    int tid = threadIdx.x;
    __shared__ float red[256];
    float v[16];
    float mx = -1e30f;
#pragma unroll
    for (int i = 0; i < 16; i++) { v[i] = ap[tid + i * 256]; mx = fmaxf(mx, v[i]); }
    red[tid] = mx; __syncthreads();
    for (int s = 128; s > 0; s >>= 1) { if (tid < s) red[tid] = fmaxf(red[tid], red[tid + s]); __syncthreads(); }
    mx = red[0]; __syncthreads();
    float sum = 0.f;
#pragma unroll
    for (int i = 0; i < 16; i++) { v[i] = expf(v[i] - mx); sum += v[i]; }
    red[tid] = sum; __syncthreads();
    for (int s = 128; s > 0; s >>= 1) { if (tid < s) red[tid] += red[tid + s]; __syncthreads(); }
    float inv = 1.0f / red[0];
#pragma unroll
    for (int i = 0; i < 16; i++) ap[tid + i * 256] = v[i] * inv;
}

// ---------------- attention pass 3: partial AV over 128-key chunks ------------
__global__ __launch_bounds__(256) void attn_av(const float* __restrict__ attn,
                                               const float* __restrict__ Vp,
                                               float* __restrict__ part)
{
    int cz = blockIdx.x, h = blockIdx.y, b = blockIdx.z;
    int bh = b * Hh + h;
    int k0 = cz * 128;
    __shared__ float As[Uu][128];
    for (int i = threadIdx.x; i < Uu * 128; i += 256) {
        int u = i >> 7, k = i & 127;
        As[u][k] = attn[((size_t)(bh * Uu + u)) * Ll + k0 + k];
    }
    __syncthreads();
    int d = threadIdx.x & 63, g = threadIdx.x >> 6;
    float acc[12];
#pragma unroll
    for (int i = 0; i < 12; i++) acc[i] = 0.f;
    for (int k = 0; k < 128; k++) {
        float v = Vp[((size_t)(b * Ll + k0 + k) * Hh + h) * DK + d];
#pragma unroll
        for (int i = 0; i < 12; i++) {
            int u = g + i * 4;
            if (u < Uu) acc[i] += As[u][k] * v;
        }
    }
#pragma unroll
    for (int i = 0; i < 12; i++) {
        int u = g + i * 4;
        if (u < Uu) part[(((size_t)bh * 32 + cz) * Uu + u) * 64 + d] = acc[i];
    }
}

// ---------------- attention pass 4: reduce + bf16 scatter ---------------------
__global__ void attn_scatter(const float* __restrict__ part, const int* __restrict__ top,
                             __nv_bfloat16* __restrict__ ctxH, __nv_bfloat16* __restrict__ ctxL)
{
    int blk = blockIdx.x;
    int bh = blk / Uu, u = blk % Uu;
    int d = threadIdx.x;
    float s = 0.f;
    for (int c = 0; c < 32; c++) s += part[(((size_t)bh * 32 + c) * Uu + u) * 64 + d];
    int b = bh >> 3, h = bh & 7;
    int l = top[bh * Uu + u];
    size_t idx = ((size_t)(b * Ll + l) * Hh + h) * DK + d;
    __nv_bfloat16 th = __float2bfloat16(s);
    ctxH[idx] = th;
    ctxL[idx] = __float2bfloat16(s - __bfloat162float(th));
}

// ---------------- launch ------------------------------------------------------
extern "C" void kernel_launch(void* const* d_in, const int* in_sizes, int n_in,
                              void* d_out, int out_size)
{
    const float* queries = (const float*)d_in[0];
    const float* keys    = (const float*)d_in[1];
    const float* values  = (const float*)d_in[2];
    const int*   sample  = (const int*)d_in[3];
    const float* Wq = (const float*)d_in[4];  const float* bq = (const float*)d_in[5];
    const float* Wk = (const float*)d_in[6];  const float* bk = (const float*)d_in[7];
    const float* Wv = (const float*)d_in[8];  const float* bv = (const float*)d_in[9];
    const float* Wo = (const float*)d_in[10]; const float* bo = (const float*)d_in[11];

    float* out      = (float*)d_out;
    float* attn_out = out + (size_t)MK;

    __nv_bfloat16 *XH, *XL, *X2, *WtH, *WtL, *Wt2, *ctxH, *ctxL;
    float *P, *M, *vpart, *vmean, *part;
    int *top;
    cudaGetSymbolAddress((void**)&XH, g_XH);
    cudaGetSymbolAddress((void**)&XL, g_XL);
    cudaGetSymbolAddress((void**)&X2, g_X2);
    cudaGetSymbolAddress((void**)&WtH, g_WtH);
    cudaGetSymbolAddress((void**)&WtL, g_WtL);
    cudaGetSymbolAddress((void**)&Wt2, g_Wt2);
    cudaGetSymbolAddress((void**)&P, g_P);
    cudaGetSymbolAddress((void**)&ctxH, g_ctxH);
    cudaGetSymbolAddress((void**)&ctxL, g_ctxL);
    cudaGetSymbolAddress((void**)&M, g_M);
    cudaGetSymbolAddress((void**)&vpart, g_vpart);
    cudaGetSymbolAddress((void**)&vmean, g_vmean);
    cudaGetSymbolAddress((void**)&top, g_top);
    cudaGetSymbolAddress((void**)&part, g_part);

    cudaFuncSetAttribute(gemm_qk6,  cudaFuncAttributeMaxDynamicSharedMemorySize, QK6_SMEM);
    cudaFuncSetAttribute(gemm_hmma, cudaFuncAttributeMaxDynamicSharedMemorySize, GEMM_SMEM);
    cudaFuncSetAttribute(gemm_out,  cudaFuncAttributeMaxDynamicSharedMemorySize, GEMM_SMEM);

    const float* Qp = P;
    const float* Kp = P + MK;
    const float* Vp = P + 2 * (size_t)MK;

    // 1. split inputs + weights
    conv_split3_all<<<dim3((MK / 4) / 256, 1, 3), 256>>>(queries, keys, values, XH, XL, X2);
    conv_w3_all<<<dim3(16, 16, 4), dim3(32, 8)>>>(Wq, Wk, Wv, Wo, WtH, WtL, Wt2);

    // 2. projections: V (3-term pairwise, verified) then Q,K (grouped 6-term)
    gemm_hmma<<<dim3(128, 4, 1), 256, GEMM_SMEM>>>(XH, XL, X2, WtH, WtL, Wt2,
                                                   bq, bk, bv, P, 2);
    gemm_qk6<<<dim3(128, 4, 2), 256, QK6_SMEM>>>(XH, XL, X2, WtH, WtL, Wt2, bq, bk, P);

    // 3. V mean (coalesced) + ctx broadcast
    vmean1<<<dim3(Bb, 32), 256>>>(Vp, vpart);
    vmean2<<<Bb, 512>>>(vpart, vmean);
    fill_ctx2<<<(MK / 4) / 256, 256>>>(vmean, ctxH, ctxL);

    // 4. sparse metric + top-k
    metric_kernel<<<dim3(Ll / 256, Hh, Bb), 256>>>(Qp, Kp, sample, M);
    topk_kernel<<<Bb * Hh, 1024>>>(M, top);

    // 5. attention multi-pass
    attn_scores<<<dim3(Ll / 256, Hh, Bb), 256>>>(Qp, Kp, top, attn_out);
    attn_softmax<<<Bb * Hh * Uu, 256>>>(attn_out);
    attn_av<<<dim3(32, Hh, Bb), 256>>>(attn_out, Vp, part);
    attn_scatter<<<Bb * Hh * Uu, 64>>>(part, top, ctxH, ctxL);

    // 6. output GEMM (3-term from ctxH/ctxL)
    gemm_out<<<dim3(128, 4, 1), 256, GEMM_SMEM>>>(ctxH, ctxL, WtH + 3 * WSZ, WtL + 3 * WSZ,
                                                  bo, out);
}

// round 13
// speedup vs baseline: 1.5532x; 1.5532x over previous
#include <cuda_runtime.h>
#include <cuda_bf16.h>
#include <cstdint>
#include <math.h>

#define Bb 4
#define Ll 4096
#define Dd 512
#define Hh 8
#define DK 64
#define Uu 45
#define SCALE 0.125f
#define MM 16384
#define MK 8388608
#define WSZ 262144

// ---------------- PTX helpers (plain-sm_103-legal) ---------------------------
__device__ __forceinline__ uint32_t smem_u32(const void* p) {
    uint32_t a;
    asm("{ .reg .u64 t; cvta.to.shared.u64 t, %1; cvt.u32.u64 %0, t; }" : "=r"(a) : "l"(p));
    return a;
}
#define CP_ASYNC16(dst, src) \
    asm volatile("cp.async.cg.shared.global [%0], [%1], 16;" :: "r"(dst), "l"(src))
#define CP_COMMIT() asm volatile("cp.async.commit_group;" ::: "memory")
#define CP_WAIT1()  asm volatile("cp.async.wait_group 1;" ::: "memory")

__device__ __forceinline__ void ldsm_x4(uint32_t* r, uint32_t addr) {
    asm volatile("ldmatrix.sync.aligned.m8n8.x4.shared.b16 {%0,%1,%2,%3}, [%4];"
        : "=r"(r[0]), "=r"(r[1]), "=r"(r[2]), "=r"(r[3]) : "r"(addr));
}
__device__ __forceinline__ void mma_bf16(float* d, const uint32_t* a, uint32_t b0, uint32_t b1) {
    asm volatile("mma.sync.aligned.m16n8k16.row.col.f32.bf16.bf16.f32 "
        "{%0,%1,%2,%3}, {%4,%5,%6,%7}, {%8,%9}, {%0,%1,%2,%3};"
        : "+f"(d[0]), "+f"(d[1]), "+f"(d[2]), "+f"(d[3])
        : "r"(a[0]), "r"(a[1]), "r"(a[2]), "r"(a[3]), "r"(b0), "r"(b1));
}

// ---------------- scratch ----------------------------------------------------
__device__ __nv_bfloat16 g_XH[3 * MK];
__device__ __nv_bfloat16 g_XL[3 * MK];
__device__ __nv_bfloat16 g_X2[3 * MK];
__device__ __nv_bfloat16 g_WtH[3 * WSZ];
__device__ __nv_bfloat16 g_WtL[3 * WSZ];
__device__ __nv_bfloat16 g_Wt2[3 * WSZ];
__device__ float g_P[3 * MK];              // Qp | Kp | Vp, (B,L,H,dk)
__device__ float g_M[Bb * Hh * Ll];
__device__ float g_vpart[Bb * 32 * Dd];
__device__ float g_vmean[Bb * Dd];
__device__ float g_base[Bb * Dd];
__device__ int   g_top[Bb * Hh * Uu];
__device__ float g_part[32 * 32 * Uu * DK];   // [bh][chunk][u][d]
__device__ float g_delta[Bb * Hh * Uu * DK];  // new_ctx - vmean per selected row

// ---------------- 3-level split, all inputs in one launch --------------------
__global__ __launch_bounds__(256) void conv_split3_all(
    const float* __restrict__ q, const float* __restrict__ k, const float* __restrict__ v,
    __nv_bfloat16* __restrict__ H, __nv_bfloat16* __restrict__ L,
    __nv_bfloat16* __restrict__ X2)
{
    int z = blockIdx.z;
    int i = blockIdx.x * 256 + threadIdx.x;
    const float* src = (z == 0) ? q : (z == 1) ? k : v;
    float4 val = ((const float4*)src)[i];
    size_t o = (size_t)z * (MK / 4) + i;
    float vv[4] = {val.x, val.y, val.z, val.w};
    __nv_bfloat16 hh[4], mm[4], ll[4];
#pragma unroll
    for (int j = 0; j < 4; j++) {
        hh[j] = __float2bfloat16(vv[j]);
        float r1 = vv[j] - __bfloat162float(hh[j]);
        mm[j] = __float2bfloat16(r1);
        ll[j] = __float2bfloat16(r1 - __bfloat162float(mm[j]));
    }
    ((__nv_bfloat162*)H)[2 * o + 0] = __halves2bfloat162(hh[0], hh[1]);
    ((__nv_bfloat162*)H)[2 * o + 1] = __halves2bfloat162(hh[2], hh[3]);
    ((__nv_bfloat162*)L)[2 * o + 0] = __halves2bfloat162(mm[0], mm[1]);
    ((__nv_bfloat162*)L)[2 * o + 1] = __halves2bfloat162(mm[2], mm[3]);
    if (z < 2) {
        ((__nv_bfloat162*)X2)[2 * o + 0] = __halves2bfloat162(ll[0], ll[1]);
        ((__nv_bfloat162*)X2)[2 * o + 1] = __halves2bfloat162(ll[2], ll[3]);
    }
}

// ---------------- weight transpose + 3-level split (Q,K,V only) --------------
__global__ void conv_w3_all(const float* __restrict__ Wq, const float* __restrict__ Wk,
                            const float* __restrict__ Wv,
                            __nv_bfloat16* __restrict__ WtH,
                            __nv_bfloat16* __restrict__ WtL,
                            __nv_bfloat16* __restrict__ Wt2)
{
    __shared__ float t[32][33];
    int z = blockIdx.z;
    const float* W = (z == 0) ? Wq : (z == 1) ? Wk : Wv;
    size_t base = (size_t)z * WSZ;
    int n0 = blockIdx.x * 32, k0 = blockIdx.y * 32;
    int tx = threadIdx.x, ty = threadIdx.y;
#pragma unroll
    for (int i = 0; i < 4; i++)
        t[ty + i * 8][tx] = W[(size_t)(k0 + ty + i * 8) * 512 + n0 + tx];
    __syncthreads();
#pragma unroll
    for (int i = 0; i < 4; i++) {
        int n = n0 + ty + i * 8;
        float v = t[tx][ty + i * 8];
        __nv_bfloat16 hb = __float2bfloat16(v);
        float r1 = v - __bfloat162float(hb);
        __nv_bfloat16 mb = __float2bfloat16(r1);
        WtH[base + (size_t)n * 512 + k0 + tx] = hb;
        WtL[base + (size_t)n * 512 + k0 + tx] = mb;
        Wt2[base + (size_t)n * 512 + k0 + tx] = __float2bfloat16(r1 - __bfloat162float(mb));
    }
}

// ---------------- pairwise HMMA GEMM (round-11 verified) ---------------------
__device__ __constant__ int c_tA[6] = {0, 0, 1, 0, 2, 1};
__device__ __constant__ int c_tB[6] = {0, 1, 0, 2, 0, 1};
#define LDAB 40
#define STG_BYTES (128 * LDAB * 2)
#define GEMM_SMEM (3 * 2 * STG_BYTES)

__global__ __launch_bounds__(256, 2) void gemm_hmma(
    const __nv_bfloat16* __restrict__ A0, const __nv_bfloat16* __restrict__ A1,
    const __nv_bfloat16* __restrict__ A2,
    const __nv_bfloat16* __restrict__ B0, const __nv_bfloat16* __restrict__ B1,
    const __nv_bfloat16* __restrict__ B2,
    const float* __restrict__ bi0, const float* __restrict__ bi1, const float* __restrict__ bi2,
    float* __restrict__ Cout)
{
    extern __shared__ char sm[];
    const int tid = threadIdx.x;
    const int w = tid >> 5, lane = tid & 31;
    const int z = blockIdx.z;
    const int m0 = blockIdx.x * 128, n0 = blockIdx.y * 128;
    const int nt = (z == 2) ? 3 : 6;
    const int NCH = nt * 16;

    const __nv_bfloat16* Alev[3] = {A0 + (size_t)z * MK, A1 + (size_t)z * MK, A2 + (size_t)z * MK};
    const __nv_bfloat16* Blev[3] = {B0 + (size_t)z * WSZ, B1 + (size_t)z * WSZ, B2 + (size_t)z * WSZ};

    const int m_off = (w >> 2) * 64, n_off = (w & 3) * 32;
    const int mi = lane >> 3, r8 = lane & 7;

    float acc[4][4][4];
#pragma unroll
    for (int i = 0; i < 4; i++)
#pragma unroll
        for (int j = 0; j < 4; j++)
#pragma unroll
            for (int q = 0; q < 4; q++) acc[i][j][q] = 0.f;

    const uint32_t sbase = smem_u32(sm);
    const int lrow = tid >> 2;
    const int lcg  = (tid & 3) * 8;

    auto load_chunk = [&](int c, int stg) {
        int t = c >> 4, k0 = (c & 15) * 32;
        const __nv_bfloat16* Asrc = Alev[c_tA[t]];
        const __nv_bfloat16* Bsrc = Blev[c_tB[t]];
        uint32_t sA = sbase + stg * (2 * STG_BYTES);
        uint32_t sB = sA + STG_BYTES;
#pragma unroll
        for (int i = 0; i < 2; i++) {
            int row = lrow + i * 64;
            CP_ASYNC16(sA + (row * LDAB + lcg) * 2, Asrc + (size_t)(m0 + row) * 512 + k0 + lcg);
            CP_ASYNC16(sB + (row * LDAB + lcg) * 2, Bsrc + (size_t)(n0 + row) * 512 + k0 + lcg);
        }
    };

    load_chunk(0, 0); CP_COMMIT();
    load_chunk(1, 1); CP_COMMIT();

    int buf = 0, pre = 2;
    for (int c = 0; c < NCH; c++) {
        CP_WAIT1();
        __syncthreads();
        if (c + 2 < NCH) load_chunk(c + 2, pre);
        CP_COMMIT();

        uint32_t sA = sbase + buf * (2 * STG_BYTES);
        uint32_t sB = sA + STG_BYTES;
#pragma unroll
        for (int kk = 0; kk < 2; kk++) {
            uint32_t a[4][4], b[2][4];
#pragma unroll
            for (int i = 0; i < 4; i++)
                ldsm_x4(a[i], sA + (uint32_t)(m_off + i * 16 + ((mi & 1) << 3) + r8) * 80
                              + kk * 32 + ((mi >> 1) << 4));
#pragma unroll
            for (int jg = 0; jg < 2; jg++)
                ldsm_x4(b[jg], sB + (uint32_t)(n_off + jg * 16 + ((mi >> 1) << 3) + r8) * 80
                               + kk * 32 + ((mi & 1) << 4));
#pragma unroll
            for (int i = 0; i < 4; i++)
#pragma unroll
                for (int j = 0; j < 4; j++)
                    mma_bf16(acc[i][j], a[i], b[j >> 1][(j & 1) * 2], b[j >> 1][(j & 1) * 2 + 1]);
        }
        buf = (buf == 2) ? 0 : buf + 1;
        pre = (pre == 2) ? 0 : pre + 1;
    }

    const float* bs = (z == 0) ? bi0 : (z == 1) ? bi1 : bi2;
    float* Cz = Cout + (size_t)z * MK;
#pragma unroll
    for (int i = 0; i < 4; i++) {
        int row0 = m0 + m_off + i * 16 + (lane >> 2);
#pragma unroll
        for (int j = 0; j < 4; j++) {
            int col = n0 + n_off + j * 8 + (lane & 3) * 2;
            float bx = bs[col], by = bs[col + 1];
            float2 v0 = make_float2(acc[i][j][0] + bx, acc[i][j][1] + by);
            float2 v1 = make_float2(acc[i][j][2] + bx, acc[i][j][3] + by);
            *(float2*)(Cz + (size_t)row0 * 512 + col) = v0;
            *(float2*)(Cz + (size_t)(row0 + 8) * 512 + col) = v1;
        }
    }
}

// ---------------- V mean: coalesced two-stage --------------------------------
__global__ __launch_bounds__(256) void vmean1(const float* __restrict__ Vp, float* __restrict__ vpart)
{
    int b = blockIdx.x, c = blockIdx.y;
    int col4 = threadIdx.x & 127;
    int half = threadIdx.x >> 7;
    const float4* base = (const float4*)(Vp + (size_t)(b * Ll + c * 128) * Dd);
    float4 acc = make_float4(0.f, 0.f, 0.f, 0.f);
    for (int r = half; r < 128; r += 2) {
        float4 v = base[(size_t)r * 128 + col4];
        acc.x += v.x; acc.y += v.y; acc.z += v.z; acc.w += v.w;
    }
    __shared__ float4 smv[128];
    if (half == 1) smv[col4] = acc;
    __syncthreads();
    if (half == 0) {
        float4 o = smv[col4];
        o.x += acc.x; o.y += acc.y; o.z += acc.z; o.w += acc.w;
        ((float4*)vpart)[((size_t)(b * 32 + c)) * 128 + col4] = o;
    }
}

__global__ void vmean2(const float* __restrict__ vpart, float* __restrict__ vmean)
{
    int b = blockIdx.x, d = threadIdx.x;
    float s = 0.f;
    for (int c = 0; c < 32; c++) s += vpart[((size_t)(b * 32 + c)) * 512 + d];
    vmean[b * Dd + d] = s * (1.0f / Ll);
}

// ---------------- base output row: vmean @ Wo + bo ----------------------------
__global__ void base_out_kernel(const float* __restrict__ vmean, const float* __restrict__ Wo,
                                const float* __restrict__ bo, float* __restrict__ baseo)
{
    int b = blockIdx.x;
    int col = blockIdx.y * 256 + threadIdx.x;
    float s = bo[col];
    for (int k = 0; k < Dd; k++)
        s += vmean[b * Dd + k] * Wo[(size_t)k * Dd + col];
    baseo[b * Dd + col] = s;
}

// ---------------- broadcast base row into out ---------------------------------
__global__ __launch_bounds__(256) void bcast_out(const float* __restrict__ baseo,
                                                 float* __restrict__ out)
{
    int i = blockIdx.x * 256 + threadIdx.x;            // float4 index into MK
    int b4 = i / (Ll * Dd / 4);
    int c4 = i % (Dd / 4);
    ((float4*)out)[i] = ((const float4*)baseo)[b4 * (Dd / 4) + c4];
}

// ---------------- sparse metric (d-tiled) ------------------------------------
__global__ __launch_bounds__(256) void metric_kernel(const float* __restrict__ Qp,
                                                     const float* __restrict__ Kp,
                                                     const int* __restrict__ sample_idx,
                                                     float* __restrict__ Mout)
{
    int b = blockIdx.z, h = blockIdx.y;
    int l = blockIdx.x * 256 + threadIdx.x;
    __shared__ float Ks[Uu * DK];
    for (int i = threadIdx.x; i < Uu * DK; i += 256) {
        int j = i / DK, d = i % DK;
        int ksl = sample_idx[j];
        Ks[i] = Kp[((size_t)(b * Ll + ksl) * Hh + h) * DK + d];
    }
    __syncthreads();
    const float* qp = &Qp[((size_t)(b * Ll + l) * Hh + h) * DK];
    float acc[Uu];
#pragma unroll
    for (int u = 0; u < Uu; u++) acc[u] = 0.f;
    for (int d0 = 0; d0 < DK; d0 += 8) {
        float4 a0 = *(const float4*)(qp + d0);
        float4 a1 = *(const float4*)(qp + d0 + 4);
#pragma unroll
        for (int u = 0; u < Uu; u++) {
            float4 b0 = *(const float4*)&Ks[u * DK + d0];
            float4 b1 = *(const float4*)&Ks[u * DK + d0 + 4];
            acc[u] += a0.x * b0.x + a0.y * b0.y + a0.z * b0.z + a0.w * b0.w
                    + a1.x * b1.x + a1.y * b1.y + a1.z * b1.z + a1.w * b1.w;
        }
    }
    float mx = -1e30f, sum = 0.f;
#pragma unroll
    for (int u = 0; u < Uu; u++) { mx = fmaxf(mx, acc[u]); sum += acc[u]; }
    Mout[(b * Hh + h) * Ll + l] = mx - sum * (1.0f / Uu);
}

// ---------------- top-45: register-resident + warp shuffles -------------------
__global__ __launch_bounds__(1024) void topk_kernel(const float* __restrict__ Min, int* __restrict__ top)
{
    int bh = blockIdx.x;
    int tid = threadIdx.x;
    int lane = tid & 31, wrp = tid >> 5;
    float4 vv = ((const float4*)(Min + (size_t)bh * Ll))[tid];
    float v[4] = {vv.x, vv.y, vv.z, vv.w};
    __shared__ float swv[32];
    __shared__ int   swi[32];
    __shared__ int   sbwi;

    for (int it = 0; it < Uu; it++) {
        float bv = v[0]; int bj = 0;
#pragma unroll
        for (int j = 1; j < 4; j++) if (v[j] > bv) { bv = v[j]; bj = j; }
        int bi = tid * 4 + bj;
#pragma unroll
        for (int s = 16; s > 0; s >>= 1) {
            float ov = __shfl_down_sync(0xffffffffu, bv, s);
            int   oi = __shfl_down_sync(0xffffffffu, bi, s);
            if (ov > bv || (ov == bv && oi < bi)) { bv = ov; bi = oi; }
        }
        if (lane == 0) { swv[wrp] = bv; swi[wrp] = bi; }
        __syncthreads();
        if (wrp == 0) {
            bv = swv[lane]; bi = swi[lane];
#pragma unroll
            for (int s = 16; s > 0; s >>= 1) {
                float ov = __shfl_down_sync(0xffffffffu, bv, s);
                int   oi = __shfl_down_sync(0xffffffffu, bi, s);
                if (ov > bv || (ov == bv && oi < bi)) { bv = ov; bi = oi; }
            }
            if (lane == 0) { sbwi = bi; top[bh * Uu + it] = bi; }
        }
        __syncthreads();
        int widx = sbwi;
        if ((widx >> 2) == tid) v[widx & 3] = -1e38f;
    }
}

// ---------------- attention pass 1: raw scaled scores -------------------------
__global__ __launch_bounds__(256) void attn_scores(const float* __restrict__ Qp,
                                                   const float* __restrict__ Kp,
                                                   const int* __restrict__ top,
                                                   float* __restrict__ attn)
{
    int kc = blockIdx.x, h = blockIdx.y, b = blockIdx.z;
    int bh = b * Hh + h;
    __shared__ float Qs[Uu * DK];
    for (int i = threadIdx.x; i < Uu * DK; i += 256) {
        int u = i >> 6, d = i & 63;
        int lsel = top[bh * Uu + u];
        Qs[i] = Qp[((size_t)(b * Ll + lsel) * Hh + h) * DK + d];
    }
    __syncthreads();
    int k = kc * 256 + threadIdx.x;
    const float* kp = Kp + ((size_t)(b * Ll + k) * Hh + h) * DK;
    float acc[Uu];
#pragma unroll
    for (int u = 0; u < Uu; u++) acc[u] = 0.f;
    for (int d0 = 0; d0 < DK; d0 += 8) {
        float4 k0 = *(const float4*)(kp + d0);
        float4 k1 = *(const float4*)(kp + d0 + 4);
#pragma unroll
        for (int u = 0; u < Uu; u++) {
            float4 q0 = *(const float4*)&Qs[u * DK + d0];
            float4 q1 = *(const float4*)&Qs[u * DK + d0 + 4];
            acc[u] += k0.x * q0.x + k0.y * q0.y + k0.z * q0.z + k0.w * q0.w
                    + k1.x * q1.x + k1.y * q1.y + k1.z * q1.z + k1.w * q1.w;
        }
    }
    float* ap = attn + (size_t)bh * Uu * Ll + k;
#pragma unroll
    for (int u = 0; u < Uu; u++) ap[(size_t)u * Ll] = acc[u] * SCALE;
}

// ---------------- attention pass 2: softmax in place --------------------------
__global__ __launch_bounds__(256) void attn_softmax(float* __restrict__ attn)
{
    size_t row = blockIdx.x;
    float* ap = attn + row * Ll;
    int tid = threadIdx.x;
    __shared__ float red[256];
    float v[16];
    float mx = -1e30f;
#pragma unroll
    for (int i = 0; i < 16; i++) { v[i] = ap[tid + i * 256]; mx = fmaxf(mx, v[i]); }
    red[tid] = mx; __syncthreads();
    for (int s = 128; s > 0; s >>= 1) { if (tid < s) red[tid] = fmaxf(red[tid], red[tid + s]); __syncthreads(); }
    mx = red[0]; __syncthreads();
    float sum = 0.f;
#pragma unroll
    for (int i = 0; i < 16; i++) { v[i] = expf(v[i] - mx); sum += v[i]; }
    red[tid] = sum; __syncthreads();
    for (int s = 128; s > 0; s >>= 1) { if (tid < s) red[tid] += red[tid + s]; __syncthreads(); }
    float inv = 1.0f / red[0];
#pragma unroll
    for (int i = 0; i < 16; i++) ap[tid + i * 256] = v[i] * inv;
}

// ---------------- attention pass 3: partial AV over 128-key chunks ------------
__global__ __launch_bounds__(256) void attn_av(const float* __restrict__ attn,
                                               const float* __restrict__ Vp,
                                               float* __restrict__ part)
{
    int cz = blockIdx.x, h = blockIdx.y, b = blockIdx.z;
    int bh = b * Hh + h;
    int k0 = cz * 128;
    __shared__ float As[Uu][128];
    for (int i = threadIdx.x; i < Uu * 128; i += 256) {
        int u = i >> 7, k = i & 127;
        As[u][k] = attn[((size_t)(bh * Uu + u)) * Ll + k0 + k];
    }
    __syncthreads();
    int d = threadIdx.x & 63, g = threadIdx.x >> 6;
    float acc[12];
#pragma unroll
    for (int i = 0; i < 12; i++) acc[i] = 0.f;
    for (int k = 0; k < 128; k++) {
        float v = Vp[((size_t)(b * Ll + k0 + k) * Hh + h) * DK + d];
#pragma unroll
        for (int i = 0; i < 12; i++) {
            int u = g + i * 4;
            if (u < Uu) acc[i] += As[u][k] * v;
        }
    }
#pragma unroll
    for (int i = 0; i < 12; i++) {
        int u = g + i * 4;
        if (u < Uu) part[(((size_t)bh * 32 + cz) * Uu + u) * 64 + d] = acc[i];
    }
}

// ---------------- attention pass 4: reduce -> delta vs vmean ------------------
__global__ void attn_delta(const float* __restrict__ part, const float* __restrict__ vmean,
                           float* __restrict__ delta)
{
    int blk = blockIdx.x;                 // 1440
    int bh = blk / Uu, u = blk % Uu;
    int d = threadIdx.x;                  // 64
    float s = 0.f;
    for (int c = 0; c < 32; c++) s += part[(((size_t)bh * 32 + c) * Uu + u) * 64 + d];
    int b = bh >> 3, h = bh & 7;
    delta[((size_t)(bh * Uu + u)) * DK + d] = s - vmean[b * Dd + h * DK + d];
}

// ---------------- correction: out[l] += delta @ Wo[h-block] (atomic) ----------
__global__ __launch_bounds__(256) void attn_correct(const float* __restrict__ delta,
                                                    const int* __restrict__ top,
                                                    const float* __restrict__ Wo,
                                                    float* __restrict__ out)
{
    int blk = blockIdx.x;                 // 1440
    int bh = blk / Uu, u = blk % Uu;
    int b = bh >> 3, h = bh & 7;
    int tid = threadIdx.x;
    __shared__ float dsh[DK];
    if (tid < DK) dsh[tid] = delta[((size_t)(bh * Uu + u)) * DK + tid];
    __syncthreads();
    int l = top[bh * Uu + u];
    float* orow = out + (size_t)(b * Ll + l) * Dd;
    const float* wbase = Wo + (size_t)(h * DK) * Dd;
#pragma unroll
    for (int rep = 0; rep < 2; rep++) {
        int col = tid + rep * 256;
        float acc = 0.f;
#pragma unroll 8
        for (int k = 0; k < DK; k++)
            acc += dsh[k] * wbase[(size_t)k * Dd + col];
        atomicAdd(&orow[col], acc);
    }
}

// ---------------- launch ------------------------------------------------------
extern "C" void kernel_launch(void* const* d_in, const int* in_sizes, int n_in,
                              void* d_out, int out_size)
{
    const float* queries = (const float*)d_in[0];
    const float* keys    = (const float*)d_in[1];
    const float* values  = (const float*)d_in[2];
    const int*   sample  = (const int*)d_in[3];
    const float* Wq = (const float*)d_in[4];  const float* bq = (const float*)d_in[5];
    const float* Wk = (const float*)d_in[6];  const float* bk = (const float*)d_in[7];
    const float* Wv = (const float*)d_in[8];  const float* bv = (const float*)d_in[9];
    const float* Wo = (const float*)d_in[10]; const float* bo = (const float*)d_in[11];

    float* out      = (float*)d_out;
    float* attn_out = out + (size_t)MK;

    __nv_bfloat16 *XH, *XL, *X2, *WtH, *WtL, *Wt2;
    float *P, *M, *vpart, *vmean, *baseo, *part, *delta;
    int *top;
    cudaGetSymbolAddress((void**)&XH, g_XH);
    cudaGetSymbolAddress((void**)&XL, g_XL);
    cudaGetSymbolAddress((void**)&X2, g_X2);
    cudaGetSymbolAddress((void**)&WtH, g_WtH);
    cudaGetSymbolAddress((void**)&WtL, g_WtL);
    cudaGetSymbolAddress((void**)&Wt2, g_Wt2);
    cudaGetSymbolAddress((void**)&P, g_P);
    cudaGetSymbolAddress((void**)&M, g_M);
    cudaGetSymbolAddress((void**)&vpart, g_vpart);
    cudaGetSymbolAddress((void**)&vmean, g_vmean);
    cudaGetSymbolAddress((void**)&baseo, g_base);
    cudaGetSymbolAddress((void**)&top, g_top);
    cudaGetSymbolAddress((void**)&part, g_part);
    cudaGetSymbolAddress((void**)&delta, g_delta);

    cudaFuncSetAttribute(gemm_hmma, cudaFuncAttributeMaxDynamicSharedMemorySize, GEMM_SMEM);

    const float* Qp = P;
    const float* Kp = P + MK;
    const float* Vp = P + 2 * (size_t)MK;

    // 1. split inputs + weights (Q,K,V only; Wo stays fp32)
    conv_split3_all<<<dim3((MK / 4) / 256, 1, 3), 256>>>(queries, keys, values, XH, XL, X2);
    conv_w3_all<<<dim3(16, 16, 3), dim3(32, 8)>>>(Wq, Wk, Wv, WtH, WtL, Wt2);

    // 2. projections: Q,K = 6-term, V = 3-term (round-11 verified GEMM)
    gemm_hmma<<<dim3(128, 4, 3), 256, GEMM_SMEM>>>(XH, XL, X2, WtH, WtL, Wt2, bq, bk, bv, P);

    // 3. V mean + base output row + broadcast into out
    vmean1<<<dim3(Bb, 32), 256>>>(Vp, vpart);
    vmean2<<<Bb, 512>>>(vpart, vmean);
    base_out_kernel<<<dim3(Bb, 2), 256>>>(vmean, Wo, bo, baseo);
    bcast_out<<<(MK / 4) / 256, 256>>>(baseo, out);

    // 4. sparse metric + top-k
    metric_kernel<<<dim3(Ll / 256, Hh, Bb), 256>>>(Qp, Kp, sample, M);
    topk_kernel<<<Bb * Hh, 1024>>>(M, top);

    // 5. attention multi-pass -> delta
    attn_scores<<<dim3(Ll / 256, Hh, Bb), 256>>>(Qp, Kp, top, attn_out);
    attn_softmax<<<Bb * Hh * Uu, 256>>>(attn_out);
    attn_av<<<dim3(32, Hh, Bb), 256>>>(attn_out, Vp, part);
    attn_delta<<<Bb * Hh * Uu, 64>>>(part, vmean, delta);

    // 6. sparse correction into out (replaces full output GEMM)
    attn_correct<<<Bb * Hh * Uu, 256>>>(delta, top, Wo, out);
}

// round 14
// speedup vs baseline: 1.5730x; 1.0127x over previous
#include <cuda_runtime.h>
#include <cuda_bf16.h>
#include <cstdint>
#include <math.h>

#define Bb 4
#define Ll 4096
#define Dd 512
#define Hh 8
#define DK 64
#define Uu 45
#define SCALE 0.125f
#define MM 16384
#define MK 8388608
#define WSZ 262144

// ---------------- PTX helpers (plain-sm_103-legal) ---------------------------
__device__ __forceinline__ uint32_t smem_u32(const void* p) {
    uint32_t a;
    asm("{ .reg .u64 t; cvta.to.shared.u64 t, %1; cvt.u32.u64 %0, t; }" : "=r"(a) : "l"(p));
    return a;
}
#define CP_ASYNC16(dst, src) \
    asm volatile("cp.async.cg.shared.global [%0], [%1], 16;" :: "r"(dst), "l"(src))
#define CP_COMMIT() asm volatile("cp.async.commit_group;" ::: "memory")
#define CP_WAIT2()  asm volatile("cp.async.wait_group 2;" ::: "memory")

__device__ __forceinline__ void ldsm_x4(uint32_t* r, uint32_t addr) {
    asm volatile("ldmatrix.sync.aligned.m8n8.x4.shared.b16 {%0,%1,%2,%3}, [%4];"
        : "=r"(r[0]), "=r"(r[1]), "=r"(r[2]), "=r"(r[3]) : "r"(addr));
}
__device__ __forceinline__ void mma_bf16(float* d, const uint32_t* a, uint32_t b0, uint32_t b1) {
    asm volatile("mma.sync.aligned.m16n8k16.row.col.f32.bf16.bf16.f32 "
        "{%0,%1,%2,%3}, {%4,%5,%6,%7}, {%8,%9}, {%0,%1,%2,%3};"
        : "+f"(d[0]), "+f"(d[1]), "+f"(d[2]), "+f"(d[3])
        : "r"(a[0]), "r"(a[1]), "r"(a[2]), "r"(a[3]), "r"(b0), "r"(b1));
}

// ---------------- scratch ----------------------------------------------------
__device__ __nv_bfloat16 g_XH[3 * MK];
__device__ __nv_bfloat16 g_XL[3 * MK];
__device__ __nv_bfloat16 g_X2[3 * MK];
__device__ __nv_bfloat16 g_WtH[3 * WSZ];
__device__ __nv_bfloat16 g_WtL[3 * WSZ];
__device__ __nv_bfloat16 g_Wt2[3 * WSZ];
__device__ float g_P[3 * MK];              // Qp | Kp | Vp, (B,L,H,dk)
__device__ float g_M[Bb * Hh * Ll];
__device__ float g_vpart[Bb * 32 * Dd];
__device__ float g_vmean[Bb * Dd];
__device__ float g_base[Bb * Dd];
__device__ int   g_top[Bb * Hh * Uu];
__device__ float g_part[32 * 32 * Uu * DK];   // [bh][chunk][u][d]
__device__ float g_delta[Bb * Hh * Uu * DK];  // new_ctx - vmean per selected row

// ---------------- 3-level split, all inputs in one launch --------------------
__global__ __launch_bounds__(256) void conv_split3_all(
    const float* __restrict__ q, const float* __restrict__ k, const float* __restrict__ v,
    __nv_bfloat16* __restrict__ H, __nv_bfloat16* __restrict__ L,
    __nv_bfloat16* __restrict__ X2)
{
    int z = blockIdx.z;
    int i = blockIdx.x * 256 + threadIdx.x;
    const float* src = (z == 0) ? q : (z == 1) ? k : v;
    float4 val = ((const float4*)src)[i];
    size_t o = (size_t)z * (MK / 4) + i;
    float vv[4] = {val.x, val.y, val.z, val.w};
    __nv_bfloat16 hh[4], mm[4], ll[4];
#pragma unroll
    for (int j = 0; j < 4; j++) {
        hh[j] = __float2bfloat16(vv[j]);
        float r1 = vv[j] - __bfloat162float(hh[j]);
        mm[j] = __float2bfloat16(r1);
        ll[j] = __float2bfloat16(r1 - __bfloat162float(mm[j]));
    }
    ((__nv_bfloat162*)H)[2 * o + 0] = __halves2bfloat162(hh[0], hh[1]);
    ((__nv_bfloat162*)H)[2 * o + 1] = __halves2bfloat162(hh[2], hh[3]);
    ((__nv_bfloat162*)L)[2 * o + 0] = __halves2bfloat162(mm[0], mm[1]);
    ((__nv_bfloat162*)L)[2 * o + 1] = __halves2bfloat162(mm[2], mm[3]);
    if (z < 2) {
        ((__nv_bfloat162*)X2)[2 * o + 0] = __halves2bfloat162(ll[0], ll[1]);
        ((__nv_bfloat162*)X2)[2 * o + 1] = __halves2bfloat162(ll[2], ll[3]);
    }
}

// ---------------- weight transpose + 3-level split (Q,K,V only) --------------
__global__ void conv_w3_all(const float* __restrict__ Wq, const float* __restrict__ Wk,
                            const float* __restrict__ Wv,
                            __nv_bfloat16* __restrict__ WtH,
                            __nv_bfloat16* __restrict__ WtL,
                            __nv_bfloat16* __restrict__ Wt2)
{
    __shared__ float t[32][33];
    int z = blockIdx.z;
    const float* W = (z == 0) ? Wq : (z == 1) ? Wk : Wv;
    size_t base = (size_t)z * WSZ;
    int n0 = blockIdx.x * 32, k0 = blockIdx.y * 32;
    int tx = threadIdx.x, ty = threadIdx.y;
#pragma unroll
    for (int i = 0; i < 4; i++)
        t[ty + i * 8][tx] = W[(size_t)(k0 + ty + i * 8) * 512 + n0 + tx];
    __syncthreads();
#pragma unroll
    for (int i = 0; i < 4; i++) {
        int n = n0 + ty + i * 8;
        float v = t[tx][ty + i * 8];
        __nv_bfloat16 hb = __float2bfloat16(v);
        float r1 = v - __bfloat162float(hb);
        __nv_bfloat16 mb = __float2bfloat16(r1);
        WtH[base + (size_t)n * 512 + k0 + tx] = hb;
        WtL[base + (size_t)n * 512 + k0 + tx] = mb;
        Wt2[base + (size_t)n * 512 + k0 + tx] = __float2bfloat16(r1 - __bfloat162float(mb));
    }
}

// ---------------- pairwise HMMA GEMM, 4-stage cp.async -----------------------
__device__ __constant__ int c_tA[6] = {0, 0, 1, 0, 2, 1};
__device__ __constant__ int c_tB[6] = {0, 1, 0, 2, 0, 1};
#define LDAB 40
#define STG_BYTES (128 * LDAB * 2)
#define GEMM_SMEM (4 * 2 * STG_BYTES)        // 81920

__global__ __launch_bounds__(256, 2) void gemm_hmma(
    const __nv_bfloat16* __restrict__ A0, const __nv_bfloat16* __restrict__ A1,
    const __nv_bfloat16* __restrict__ A2,
    const __nv_bfloat16* __restrict__ B0, const __nv_bfloat16* __restrict__ B1,
    const __nv_bfloat16* __restrict__ B2,
    const float* __restrict__ bi0, const float* __restrict__ bi1, const float* __restrict__ bi2,
    float* __restrict__ Cout)
{
    extern __shared__ char sm[];
    const int tid = threadIdx.x;
    const int w = tid >> 5, lane = tid & 31;
    const int z = blockIdx.z;
    const int m0 = blockIdx.x * 128, n0 = blockIdx.y * 128;
    const int nt = (z == 2) ? 3 : 6;
    const int NCH = nt * 16;

    const __nv_bfloat16* Alev[3] = {A0 + (size_t)z * MK, A1 + (size_t)z * MK, A2 + (size_t)z * MK};
    const __nv_bfloat16* Blev[3] = {B0 + (size_t)z * WSZ, B1 + (size_t)z * WSZ, B2 + (size_t)z * WSZ};

    const int m_off = (w >> 2) * 64, n_off = (w & 3) * 32;
    const int mi = lane >> 3, r8 = lane & 7;

    float acc[4][4][4];
#pragma unroll
    for (int i = 0; i < 4; i++)
#pragma unroll
        for (int j = 0; j < 4; j++)
#pragma unroll
            for (int q = 0; q < 4; q++) acc[i][j][q] = 0.f;

    const uint32_t sbase = smem_u32(sm);
    const int lrow = tid >> 2;
    const int lcg  = (tid & 3) * 8;

    auto load_chunk = [&](int c, int stg) {
        int t = c >> 4, k0 = (c & 15) * 32;
        const __nv_bfloat16* Asrc = Alev[c_tA[t]];
        const __nv_bfloat16* Bsrc = Blev[c_tB[t]];
        uint32_t sA = sbase + stg * (2 * STG_BYTES);
        uint32_t sB = sA + STG_BYTES;
#pragma unroll
        for (int i = 0; i < 2; i++) {
            int row = lrow + i * 64;
            CP_ASYNC16(sA + (row * LDAB + lcg) * 2, Asrc + (size_t)(m0 + row) * 512 + k0 + lcg);
            CP_ASYNC16(sB + (row * LDAB + lcg) * 2, Bsrc + (size_t)(n0 + row) * 512 + k0 + lcg);
        }
    };

    load_chunk(0, 0); CP_COMMIT();
    load_chunk(1, 1); CP_COMMIT();
    load_chunk(2, 2); CP_COMMIT();

    int buf = 0, pre = 3;                 // pre = stage for chunk c+3
    for (int c = 0; c < NCH; c++) {
        CP_WAIT2();
        __syncthreads();
        if (c + 3 < NCH) load_chunk(c + 3, pre);
        CP_COMMIT();

        uint32_t sA = sbase + buf * (2 * STG_BYTES);
        uint32_t sB = sA + STG_BYTES;
#pragma unroll
        for (int kk = 0; kk < 2; kk++) {
            uint32_t a[4][4], b[2][4];
#pragma unroll
            for (int i = 0; i < 4; i++)
                ldsm_x4(a[i], sA + (uint32_t)(m_off + i * 16 + ((mi & 1) << 3) + r8) * 80
                              + kk * 32 + ((mi >> 1) << 4));
#pragma unroll
            for (int jg = 0; jg < 2; jg++)
                ldsm_x4(b[jg], sB + (uint32_t)(n_off + jg * 16 + ((mi >> 1) << 3) + r8) * 80
                               + kk * 32 + ((mi & 1) << 4));
#pragma unroll
            for (int i = 0; i < 4; i++)
#pragma unroll
                for (int j = 0; j < 4; j++)
                    mma_bf16(acc[i][j], a[i], b[j >> 1][(j & 1) * 2], b[j >> 1][(j & 1) * 2 + 1]);
        }
        buf = (buf == 3) ? 0 : buf + 1;
        pre = (pre == 3) ? 0 : pre + 1;
    }

    const float* bs = (z == 0) ? bi0 : (z == 1) ? bi1 : bi2;
    float* Cz = Cout + (size_t)z * MK;
#pragma unroll
    for (int i = 0; i < 4; i++) {
        int row0 = m0 + m_off + i * 16 + (lane >> 2);
#pragma unroll
        for (int j = 0; j < 4; j++) {
            int col = n0 + n_off + j * 8 + (lane & 3) * 2;
            float bx = bs[col], by = bs[col + 1];
            float2 v0 = make_float2(acc[i][j][0] + bx, acc[i][j][1] + by);
            float2 v1 = make_float2(acc[i][j][2] + bx, acc[i][j][3] + by);
            *(float2*)(Cz + (size_t)row0 * 512 + col) = v0;
            *(float2*)(Cz + (size_t)(row0 + 8) * 512 + col) = v1;
        }
    }
}

// ---------------- V mean: coalesced two-stage --------------------------------
__global__ __launch_bounds__(256) void vmean1(const float* __restrict__ Vp, float* __restrict__ vpart)
{
    int b = blockIdx.x, c = blockIdx.y;
    int col4 = threadIdx.x & 127;
    int half = threadIdx.x >> 7;
    const float4* base = (const float4*)(Vp + (size_t)(b * Ll + c * 128) * Dd);
    float4 acc = make_float4(0.f, 0.f, 0.f, 0.f);
    for (int r = half; r < 128; r += 2) {
        float4 v = base[(size_t)r * 128 + col4];
        acc.x += v.x; acc.y += v.y; acc.z += v.z; acc.w += v.w;
    }
    __shared__ float4 smv[128];
    if (half == 1) smv[col4] = acc;
    __syncthreads();
    if (half == 0) {
        float4 o = smv[col4];
        o.x += acc.x; o.y += acc.y; o.z += acc.z; o.w += acc.w;
        ((float4*)vpart)[((size_t)(b * 32 + c)) * 128 + col4] = o;
    }
}

__global__ void vmean2(const float* __restrict__ vpart, float* __restrict__ vmean)
{
    int b = blockIdx.x, d = threadIdx.x;
    float s = 0.f;
    for (int c = 0; c < 32; c++) s += vpart[((size_t)(b * 32 + c)) * 512 + d];
    vmean[b * Dd + d] = s * (1.0f / Ll);
}

// ---------------- base output row: vmean @ Wo + bo ----------------------------
__global__ void base_out_kernel(const float* __restrict__ vmean, const float* __restrict__ Wo,
                                const float* __restrict__ bo, float* __restrict__ baseo)
{
    int b = blockIdx.x;
    int col = blockIdx.y * 256 + threadIdx.x;
    float s = bo[col];
    for (int k = 0; k < Dd; k++)
        s += vmean[b * Dd + k] * Wo[(size_t)k * Dd + col];
    baseo[b * Dd + col] = s;
}

// ---------------- broadcast base row into out ---------------------------------
__global__ __launch_bounds__(256) void bcast_out(const float* __restrict__ baseo,
                                                 float* __restrict__ out)
{
    int i = blockIdx.x * 256 + threadIdx.x;            // float4 index into MK
    int b4 = i / (Ll * Dd / 4);
    int c4 = i % (Dd / 4);
    ((float4*)out)[i] = ((const float4*)baseo)[b4 * (Dd / 4) + c4];
}

// ---------------- sparse metric (d-tiled) ------------------------------------
__global__ __launch_bounds__(256) void metric_kernel(const float* __restrict__ Qp,
                                                     const float* __restrict__ Kp,
                                                     const int* __restrict__ sample_idx,
                                                     float* __restrict__ Mout)
{
    int b = blockIdx.z, h = blockIdx.y;
    int l = blockIdx.x * 256 + threadIdx.x;
    __shared__ float Ks[Uu * DK];
    for (int i = threadIdx.x; i < Uu * DK; i += 256) {
        int j = i / DK, d = i % DK;
        int ksl = sample_idx[j];
        Ks[i] = Kp[((size_t)(b * Ll + ksl) * Hh + h) * DK + d];
    }
    __syncthreads();
    const float* qp = &Qp[((size_t)(b * Ll + l) * Hh + h) * DK];
    float acc[Uu];
#pragma unroll
    for (int u = 0; u < Uu; u++) acc[u] = 0.f;
    for (int d0 = 0; d0 < DK; d0 += 8) {
        float4 a0 = *(const float4*)(qp + d0);
        float4 a1 = *(const float4*)(qp + d0 + 4);
#pragma unroll
        for (int u = 0; u < Uu; u++) {
            float4 b0 = *(const float4*)&Ks[u * DK + d0];
            float4 b1 = *(const float4*)&Ks[u * DK + d0 + 4];
            acc[u] += a0.x * b0.x + a0.y * b0.y + a0.z * b0.z + a0.w * b0.w
                    + a1.x * b1.x + a1.y * b1.y + a1.z * b1.z + a1.w * b1.w;
        }
    }
    float mx = -1e30f, sum = 0.f;
#pragma unroll
    for (int u = 0; u < Uu; u++) { mx = fmaxf(mx, acc[u]); sum += acc[u]; }
    Mout[(b * Hh + h) * Ll + l] = mx - sum * (1.0f / Uu);
}

// ---------------- top-45: register-resident + warp shuffles -------------------
__global__ __launch_bounds__(1024) void topk_kernel(const float* __restrict__ Min, int* __restrict__ top)
{
    int bh = blockIdx.x;
    int tid = threadIdx.x;
    int lane = tid & 31, wrp = tid >> 5;
    float4 vv = ((const float4*)(Min + (size_t)bh * Ll))[tid];
    float v[4] = {vv.x, vv.y, vv.z, vv.w};
    __shared__ float swv[32];
    __shared__ int   swi[32];
    __shared__ int   sbwi;

    for (int it = 0; it < Uu; it++) {
        float bv = v[0]; int bj = 0;
#pragma unroll
        for (int j = 1; j < 4; j++) if (v[j] > bv) { bv = v[j]; bj = j; }
        int bi = tid * 4 + bj;
#pragma unroll
        for (int s = 16; s > 0; s >>= 1) {
            float ov = __shfl_down_sync(0xffffffffu, bv, s);
            int   oi = __shfl_down_sync(0xffffffffu, bi, s);
            if (ov > bv || (ov == bv && oi < bi)) { bv = ov; bi = oi; }
        }
        if (lane == 0) { swv[wrp] = bv; swi[wrp] = bi; }
        __syncthreads();
        if (wrp == 0) {
            bv = swv[lane]; bi = swi[lane];
#pragma unroll
            for (int s = 16; s > 0; s >>= 1) {
                float ov = __shfl_down_sync(0xffffffffu, bv, s);
                int   oi = __shfl_down_sync(0xffffffffu, bi, s);
                if (ov > bv || (ov == bv && oi < bi)) { bv = ov; bi = oi; }
            }
            if (lane == 0) { sbwi = bi; top[bh * Uu + it] = bi; }
        }
        __syncthreads();
        int widx = sbwi;
        if ((widx >> 2) == tid) v[widx & 3] = -1e38f;
    }
}

// ---------------- attention pass 1: raw scaled scores -------------------------
__global__ __launch_bounds__(256) void attn_scores(const float* __restrict__ Qp,
                                                   const float* __restrict__ Kp,
                                                   const int* __restrict__ top,
                                                   float* __restrict__ attn)
{
    int kc = blockIdx.x, h = blockIdx.y, b = blockIdx.z;
    int bh = b * Hh + h;
    __shared__ float Qs[Uu * DK];
    for (int i = threadIdx.x; i < Uu * DK; i += 256) {
        int u = i >> 6, d = i & 63;
        int lsel = top[bh * Uu + u];
        Qs[i] = Qp[((size_t)(b * Ll + lsel) * Hh + h) * DK + d];
    }
    __syncthreads();
    int k = kc * 256 + threadIdx.x;
    const float* kp = Kp + ((size_t)(b * Ll + k) * Hh + h) * DK;
    float acc[Uu];
#pragma unroll
    for (int u = 0; u < Uu; u++) acc[u] = 0.f;
    for (int d0 = 0; d0 < DK; d0 += 8) {
        float4 k0 = *(const float4*)(kp + d0);
        float4 k1 = *(const float4*)(kp + d0 + 4);
#pragma unroll
        for (int u = 0; u < Uu; u++) {
            float4 q0 = *(const float4*)&Qs[u * DK + d0];
            float4 q1 = *(const float4*)&Qs[u * DK + d0 + 4];
            acc[u] += k0.x * q0.x + k0.y * q0.y + k0.z * q0.z + k0.w * q0.w
                    + k1.x * q1.x + k1.y * q1.y + k1.z * q1.z + k1.w * q1.w;
        }
    }
    float* ap = attn + (size_t)bh * Uu * Ll + k;
#pragma unroll
    for (int u = 0; u < Uu; u++) ap[(size_t)u * Ll] = acc[u] * SCALE;
}

// ---------------- attention pass 2: softmax in place --------------------------
__global__ __launch_bounds__(256) void attn_softmax(float* __restrict__ attn)
{
    size_t row = blockIdx.x;
    float* ap = attn + row * Ll;
    int tid = threadIdx.x;
    __shared__ float red[256];
    float v[16];
    float mx = -1e30f;
#pragma unroll
    for (int i = 0; i < 16; i++) { v[i] = ap[tid + i * 256]; mx = fmaxf(mx, v[i]); }
    red[tid] = mx; __syncthreads();
    for (int s = 128; s > 0; s >>= 1) { if (tid < s) red[tid] = fmaxf(red[tid], red[tid + s]); __syncthreads(); }
    mx = red[0]; __syncthreads();
    float sum = 0.f;
#pragma unroll
    for (int i = 0; i < 16; i++) { v[i] = expf(v[i] - mx); sum += v[i]; }
    red[tid] = sum; __syncthreads();
    for (int s = 128; s > 0; s >>= 1) { if (tid < s) red[tid] += red[tid + s]; __syncthreads(); }
    float inv = 1.0f / red[0];
#pragma unroll
    for (int i = 0; i < 16; i++) ap[tid + i * 256] = v[i] * inv;
}

// ---------------- attention pass 3: partial AV over 128-key chunks ------------
__global__ __launch_bounds__(256) void attn_av(const float* __restrict__ attn,
                                               const float* __restrict__ Vp,
                                               float* __restrict__ part)
{
    int cz = blockIdx.x, h = blockIdx.y, b = blockIdx.z;
    int bh = b * Hh + h;
    int k0 = cz * 128;
    __shared__ float As[Uu][128];
    for (int i = threadIdx.x; i < Uu * 128; i += 256) {
        int u = i >> 7, k = i & 127;
        As[u][k] = attn[((size_t)(bh * Uu + u)) * Ll + k0 + k];
    }
    __syncthreads();
    int d = threadIdx.x & 63, g = threadIdx.x >> 6;
    float acc[12];
#pragma unroll
    for (int i = 0; i < 12; i++) acc[i] = 0.f;
    for (int k = 0; k < 128; k++) {
        float v = Vp[((size_t)(b * Ll + k0 + k) * Hh + h) * DK + d];
#pragma unroll
        for (int i = 0; i < 12; i++) {
            int u = g + i * 4;
            if (u < Uu) acc[i] += As[u][k] * v;
        }
    }
#pragma unroll
    for (int i = 0; i < 12; i++) {
        int u = g + i * 4;
        if (u < Uu) part[(((size_t)bh * 32 + cz) * Uu + u) * 64 + d] = acc[i];
    }
}

// ---------------- attention pass 4: reduce -> delta vs vmean ------------------
__global__ void attn_delta(const float* __restrict__ part, const float* __restrict__ vmean,
                           float* __restrict__ delta)
{
    int blk = blockIdx.x;                 // 1440
    int bh = blk / Uu, u = blk % Uu;
    int d = threadIdx.x;                  // 64
    float s = 0.f;
    for (int c = 0; c < 32; c++) s += part[(((size_t)bh * 32 + c) * Uu + u) * 64 + d];
    int b = bh >> 3, h = bh & 7;
    delta[((size_t)(bh * Uu + u)) * DK + d] = s - vmean[b * Dd + h * DK + d];
}

// ---------------- correction: out[l] += delta @ Wo[h-block] (atomic) ----------
__global__ __launch_bounds__(256) void attn_correct(const float* __restrict__ delta,
                                                    const int* __restrict__ top,
                                                    const float* __restrict__ Wo,
                                                    float* __restrict__ out)
{
    int blk = blockIdx.x;                 // 1440
    int bh = blk / Uu, u = blk % Uu;
    int b = bh >> 3, h = bh & 7;
    int tid = threadIdx.x;
    __shared__ float dsh[DK];
    if (tid < DK) dsh[tid] = delta[((size_t)(bh * Uu + u)) * DK + tid];
    __syncthreads();
    int l = top[bh * Uu + u];
    float* orow = out + (size_t)(b * Ll + l) * Dd;
    const float* wbase = Wo + (size_t)(h * DK) * Dd;
#pragma unroll
    for (int rep = 0; rep < 2; rep++) {
        int col = tid + rep * 256;
        float acc = 0.f;
#pragma unroll 8
        for (int k = 0; k < DK; k++)
            acc += dsh[k] * wbase[(size_t)k * Dd + col];
        atomicAdd(&orow[col], acc);
    }
}

// ---------------- launch ------------------------------------------------------
extern "C" void kernel_launch(void* const* d_in, const int* in_sizes, int n_in,
                              void* d_out, int out_size)
{
    const float* queries = (const float*)d_in[0];
    const float* keys    = (const float*)d_in[1];
    const float* values  = (const float*)d_in[2];
    const int*   sample  = (const int*)d_in[3];
    const float* Wq = (const float*)d_in[4];  const float* bq = (const float*)d_in[5];
    const float* Wk = (const float*)d_in[6];  const float* bk = (const float*)d_in[7];
    const float* Wv = (const float*)d_in[8];  const float* bv = (const float*)d_in[9];
    const float* Wo = (const float*)d_in[10]; const float* bo = (const float*)d_in[11];

    float* out      = (float*)d_out;
    float* attn_out = out + (size_t)MK;

    __nv_bfloat16 *XH, *XL, *X2, *WtH, *WtL, *Wt2;
    float *P, *M, *vpart, *vmean, *baseo, *part, *delta;
    int *top;
    cudaGetSymbolAddress((void**)&XH, g_XH);
    cudaGetSymbolAddress((void**)&XL, g_XL);
    cudaGetSymbolAddress((void**)&X2, g_X2);
    cudaGetSymbolAddress((void**)&WtH, g_WtH);
    cudaGetSymbolAddress((void**)&WtL, g_WtL);
    cudaGetSymbolAddress((void**)&Wt2, g_Wt2);
    cudaGetSymbolAddress((void**)&P, g_P);
    cudaGetSymbolAddress((void**)&M, g_M);
    cudaGetSymbolAddress((void**)&vpart, g_vpart);
    cudaGetSymbolAddress((void**)&vmean, g_vmean);
    cudaGetSymbolAddress((void**)&baseo, g_base);
    cudaGetSymbolAddress((void**)&top, g_top);
    cudaGetSymbolAddress((void**)&part, g_part);
    cudaGetSymbolAddress((void**)&delta, g_delta);

    cudaFuncSetAttribute(gemm_hmma, cudaFuncAttributeMaxDynamicSharedMemorySize, GEMM_SMEM);

    const float* Qp = P;
    const float* Kp = P + MK;
    const float* Vp = P + 2 * (size_t)MK;

    // 1. split inputs + weights (Q,K,V only; Wo stays fp32)
    conv_split3_all<<<dim3((MK / 4) / 256, 1, 3), 256>>>(queries, keys, values, XH, XL, X2);
    conv_w3_all<<<dim3(16, 16, 3), dim3(32, 8)>>>(Wq, Wk, Wv, WtH, WtL, Wt2);

    // 2. projections: Q,K = 6-term, V = 3-term (4-stage pipeline)
    gemm_hmma<<<dim3(128, 4, 3), 256, GEMM_SMEM>>>(XH, XL, X2, WtH, WtL, Wt2, bq, bk, bv, P);

    // 3. V mean + base output row + broadcast into out
    vmean1<<<dim3(Bb, 32), 256>>>(Vp, vpart);
    vmean2<<<Bb, 512>>>(vpart, vmean);
    base_out_kernel<<<dim3(Bb, 2), 256>>>(vmean, Wo, bo, baseo);
    bcast_out<<<(MK / 4) / 256, 256>>>(baseo, out);

    // 4. sparse metric + top-k
    metric_kernel<<<dim3(Ll / 256, Hh, Bb), 256>>>(Qp, Kp, sample, M);
    topk_kernel<<<Bb * Hh, 1024>>>(M, top);

    // 5. attention multi-pass -> delta
    attn_scores<<<dim3(Ll / 256, Hh, Bb), 256>>>(Qp, Kp, top, attn_out);
    attn_softmax<<<Bb * Hh * Uu, 256>>>(attn_out);
    attn_av<<<dim3(32, Hh, Bb), 256>>>(attn_out, Vp, part);
    attn_delta<<<Bb * Hh * Uu, 64>>>(part, vmean, delta);

    // 6. sparse correction into out (replaces full output GEMM)
    attn_correct<<<Bb * Hh * Uu, 256>>>(delta, top, Wo, out);
}

// round 15
// speedup vs baseline: 1.6426x; 1.0442x over previous
#include <cuda_runtime.h>
#include <cuda_bf16.h>
#include <cstdint>
#include <math.h>

#define Bb 4
#define Ll 4096
#define Dd 512
#define Hh 8
#define DK 64
#define Uu 45
#define SCALE 0.125f
#define MM 16384
#define MK 8388608
#define WSZ 262144

// ---------------- PTX helpers (plain-sm_103-legal) ---------------------------
__device__ __forceinline__ uint32_t smem_u32(const void* p) {
    uint32_t a;
    asm("{ .reg .u64 t; cvta.to.shared.u64 t, %1; cvt.u32.u64 %0, t; }" : "=r"(a) : "l"(p));
    return a;
}
#define CP_ASYNC16(dst, src) \
    asm volatile("cp.async.cg.shared.global [%0], [%1], 16;" :: "r"(dst), "l"(src))
#define CP_COMMIT() asm volatile("cp.async.commit_group;" ::: "memory")
#define CP_WAIT1()  asm volatile("cp.async.wait_group 1;" ::: "memory")

__device__ __forceinline__ void ldsm_x4(uint32_t* r, uint32_t addr) {
    asm volatile("ldmatrix.sync.aligned.m8n8.x4.shared.b16 {%0,%1,%2,%3}, [%4];"
        : "=r"(r[0]), "=r"(r[1]), "=r"(r[2]), "=r"(r[3]) : "r"(addr));
}
__device__ __forceinline__ void mma_bf16(float* d, const uint32_t* a, uint32_t b0, uint32_t b1) {
    asm volatile("mma.sync.aligned.m16n8k16.row.col.f32.bf16.bf16.f32 "
        "{%0,%1,%2,%3}, {%4,%5,%6,%7}, {%8,%9}, {%0,%1,%2,%3};"
        : "+f"(d[0]), "+f"(d[1]), "+f"(d[2]), "+f"(d[3])
        : "r"(a[0]), "r"(a[1]), "r"(a[2]), "r"(a[3]), "r"(b0), "r"(b1));
}

// ---------------- scratch ----------------------------------------------------
__device__ __nv_bfloat16 g_XH[3 * MK];
__device__ __nv_bfloat16 g_XL[3 * MK];
__device__ __nv_bfloat16 g_X2[3 * MK];
__device__ __nv_bfloat16 g_WtH[3 * WSZ];
__device__ __nv_bfloat16 g_WtL[3 * WSZ];
__device__ __nv_bfloat16 g_Wt2[3 * WSZ];
__device__ float g_P[3 * MK];              // Qp | Kp | Vp, (B,L,H,dk)
__device__ float g_M[Bb * Hh * Ll];
__device__ float g_vpart[Bb * 32 * Dd];
__device__ float g_vmean[Bb * Dd];
__device__ float g_base[Bb * Dd];
__device__ int   g_top[Bb * Hh * Uu];
__device__ float g_part[32 * 32 * Uu * DK];   // [bh][chunk][u][d]
__device__ float g_delta[Bb * Hh * Uu * DK];  // new_ctx - vmean per selected row

// ---------------- 3-level split, all inputs in one launch --------------------
__global__ __launch_bounds__(256) void conv_split3_all(
    const float* __restrict__ q, const float* __restrict__ k, const float* __restrict__ v,
    __nv_bfloat16* __restrict__ H, __nv_bfloat16* __restrict__ L,
    __nv_bfloat16* __restrict__ X2)
{
    int z = blockIdx.z;
    int i = blockIdx.x * 256 + threadIdx.x;
    const float* src = (z == 0) ? q : (z == 1) ? k : v;
    float4 val = ((const float4*)src)[i];
    size_t o = (size_t)z * (MK / 4) + i;
    float vv[4] = {val.x, val.y, val.z, val.w};
    __nv_bfloat16 hh[4], mm[4], ll[4];
#pragma unroll
    for (int j = 0; j < 4; j++) {
        hh[j] = __float2bfloat16(vv[j]);
        float r1 = vv[j] - __bfloat162float(hh[j]);
        mm[j] = __float2bfloat16(r1);
        ll[j] = __float2bfloat16(r1 - __bfloat162float(mm[j]));
    }
    ((__nv_bfloat162*)H)[2 * o + 0] = __halves2bfloat162(hh[0], hh[1]);
    ((__nv_bfloat162*)H)[2 * o + 1] = __halves2bfloat162(hh[2], hh[3]);
    ((__nv_bfloat162*)L)[2 * o + 0] = __halves2bfloat162(mm[0], mm[1]);
    ((__nv_bfloat162*)L)[2 * o + 1] = __halves2bfloat162(mm[2], mm[3]);
    if (z < 2) {
        ((__nv_bfloat162*)X2)[2 * o + 0] = __halves2bfloat162(ll[0], ll[1]);
        ((__nv_bfloat162*)X2)[2 * o + 1] = __halves2bfloat162(ll[2], ll[3]);
    }
}

// ---------------- weight transpose + 3-level split (Q,K,V only) --------------
__global__ void conv_w3_all(const float* __restrict__ Wq, const float* __restrict__ Wk,
                            const float* __restrict__ Wv,
                            __nv_bfloat16* __restrict__ WtH,
                            __nv_bfloat16* __restrict__ WtL,
                            __nv_bfloat16* __restrict__ Wt2)
{
    __shared__ float t[32][33];
    int z = blockIdx.z;
    const float* W = (z == 0) ? Wq : (z == 1) ? Wk : Wv;
    size_t base = (size_t)z * WSZ;
    int n0 = blockIdx.x * 32, k0 = blockIdx.y * 32;
    int tx = threadIdx.x, ty = threadIdx.y;
#pragma unroll
    for (int i = 0; i < 4; i++)
        t[ty + i * 8][tx] = W[(size_t)(k0 + ty + i * 8) * 512 + n0 + tx];
    __syncthreads();
#pragma unroll
    for (int i = 0; i < 4; i++) {
        int n = n0 + ty + i * 8;
        float v = t[tx][ty + i * 8];
        __nv_bfloat16 hb = __float2bfloat16(v);
        float r1 = v - __bfloat162float(hb);
        __nv_bfloat16 mb = __float2bfloat16(r1);
        WtH[base + (size_t)n * 512 + k0 + tx] = hb;
        WtL[base + (size_t)n * 512 + k0 + tx] = mb;
        Wt2[base + (size_t)n * 512 + k0 + tx] = __float2bfloat16(r1 - __bfloat162float(mb));
    }
}

// ---------------- pairwise HMMA GEMM, K=64 chunks, 3-stage -------------------
__device__ __constant__ int c_tA[6] = {0, 0, 1, 0, 2, 1};
__device__ __constant__ int c_tB[6] = {0, 1, 0, 2, 0, 1};
#define LDAB 72                              // 64 bf16 + 8 pad (144 B rows)
#define STG_BYTES (128 * LDAB * 2)           // 18432 per tile
#define GEMM_SMEM (3 * 2 * STG_BYTES)        // 110592

__global__ __launch_bounds__(256, 2) void gemm_hmma(
    const __nv_bfloat16* __restrict__ A0, const __nv_bfloat16* __restrict__ A1,
    const __nv_bfloat16* __restrict__ A2,
    const __nv_bfloat16* __restrict__ B0, const __nv_bfloat16* __restrict__ B1,
    const __nv_bfloat16* __restrict__ B2,
    const float* __restrict__ bi0, const float* __restrict__ bi1, const float* __restrict__ bi2,
    float* __restrict__ Cout)
{
    extern __shared__ char sm[];
    const int tid = threadIdx.x;
    const int w = tid >> 5, lane = tid & 31;
    const int z = blockIdx.z;
    const int m0 = blockIdx.x * 128, n0 = blockIdx.y * 128;
    const int nt = (z == 2) ? 3 : 6;
    const int NCH = nt * 8;                  // K=64 per chunk

    const __nv_bfloat16* Alev[3] = {A0 + (size_t)z * MK, A1 + (size_t)z * MK, A2 + (size_t)z * MK};
    const __nv_bfloat16* Blev[3] = {B0 + (size_t)z * WSZ, B1 + (size_t)z * WSZ, B2 + (size_t)z * WSZ};

    const int m_off = (w >> 2) * 64, n_off = (w & 3) * 32;
    const int mi = lane >> 3, r8 = lane & 7;

    float acc[4][4][4];
#pragma unroll
    for (int i = 0; i < 4; i++)
#pragma unroll
        for (int j = 0; j < 4; j++)
#pragma unroll
            for (int q = 0; q < 4; q++) acc[i][j][q] = 0.f;

    const uint32_t sbase = smem_u32(sm);
    const int lrow = tid >> 3;               // 0..31 (+32,+64,+96)
    const int lcg  = (tid & 7) * 8;          // bf16 col within 64-wide chunk

    auto load_chunk = [&](int c, int stg) {
        int t = c >> 3, k0 = (c & 7) * 64;
        const __nv_bfloat16* Asrc = Alev[c_tA[t]];
        const __nv_bfloat16* Bsrc = Blev[c_tB[t]];
        uint32_t sA = sbase + stg * (2 * STG_BYTES);
        uint32_t sB = sA + STG_BYTES;
#pragma unroll
        for (int i = 0; i < 4; i++) {
            int row = lrow + i * 32;
            CP_ASYNC16(sA + (row * LDAB + lcg) * 2, Asrc + (size_t)(m0 + row) * 512 + k0 + lcg);
            CP_ASYNC16(sB + (row * LDAB + lcg) * 2, Bsrc + (size_t)(n0 + row) * 512 + k0 + lcg);
        }
    };

    load_chunk(0, 0); CP_COMMIT();
    load_chunk(1, 1); CP_COMMIT();

    int buf = 0, pre = 2;
    for (int c = 0; c < NCH; c++) {
        CP_WAIT1();
        __syncthreads();
        if (c + 2 < NCH) load_chunk(c + 2, pre);
        CP_COMMIT();

        uint32_t sA = sbase + buf * (2 * STG_BYTES);
        uint32_t sB = sA + STG_BYTES;
#pragma unroll
        for (int kk = 0; kk < 4; kk++) {
            uint32_t a[4][4], b[2][4];
#pragma unroll
            for (int i = 0; i < 4; i++)
                ldsm_x4(a[i], sA + (uint32_t)(m_off + i * 16 + ((mi & 1) << 3) + r8) * 144
                              + kk * 32 + ((mi >> 1) << 4));
#pragma unroll
            for (int jg = 0; jg < 2; jg++)
                ldsm_x4(b[jg], sB + (uint32_t)(n_off + jg * 16 + ((mi >> 1) << 3) + r8) * 144
                               + kk * 32 + ((mi & 1) << 4));
#pragma unroll
            for (int i = 0; i < 4; i++)
#pragma unroll
                for (int j = 0; j < 4; j++)
                    mma_bf16(acc[i][j], a[i], b[j >> 1][(j & 1) * 2], b[j >> 1][(j & 1) * 2 + 1]);
        }
        buf = (buf == 2) ? 0 : buf + 1;
        pre = (pre == 2) ? 0 : pre + 1;
    }

    const float* bs = (z == 0) ? bi0 : (z == 1) ? bi1 : bi2;
    float* Cz = Cout + (size_t)z * MK;
#pragma unroll
    for (int i = 0; i < 4; i++) {
        int row0 = m0 + m_off + i * 16 + (lane >> 2);
#pragma unroll
        for (int j = 0; j < 4; j++) {
            int col = n0 + n_off + j * 8 + (lane & 3) * 2;
            float bx = bs[col], by = bs[col + 1];
            float2 v0 = make_float2(acc[i][j][0] + bx, acc[i][j][1] + by);
            float2 v1 = make_float2(acc[i][j][2] + bx, acc[i][j][3] + by);
            *(float2*)(Cz + (size_t)row0 * 512 + col) = v0;
            *(float2*)(Cz + (size_t)(row0 + 8) * 512 + col) = v1;
        }
    }
}

// ---------------- V mean: coalesced two-stage --------------------------------
__global__ __launch_bounds__(256) void vmean1(const float* __restrict__ Vp, float* __restrict__ vpart)
{
    int b = blockIdx.x, c = blockIdx.y;
    int col4 = threadIdx.x & 127;
    int half = threadIdx.x >> 7;
    const float4* base = (const float4*)(Vp + (size_t)(b * Ll + c * 128) * Dd);
    float4 acc = make_float4(0.f, 0.f, 0.f, 0.f);
    for (int r = half; r < 128; r += 2) {
        float4 v = base[(size_t)r * 128 + col4];
        acc.x += v.x; acc.y += v.y; acc.z += v.z; acc.w += v.w;
    }
    __shared__ float4 smv[128];
    if (half == 1) smv[col4] = acc;
    __syncthreads();
    if (half == 0) {
        float4 o = smv[col4];
        o.x += acc.x; o.y += acc.y; o.z += acc.z; o.w += acc.w;
        ((float4*)vpart)[((size_t)(b * 32 + c)) * 128 + col4] = o;
    }
}

__global__ void vmean2(const float* __restrict__ vpart, float* __restrict__ vmean)
{
    int b = blockIdx.x, d = threadIdx.x;
    float s = 0.f;
    for (int c = 0; c < 32; c++) s += vpart[((size_t)(b * 32 + c)) * 512 + d];
    vmean[b * Dd + d] = s * (1.0f / Ll);
}

// ---------------- base output row: vmean @ Wo + bo ----------------------------
__global__ void base_out_kernel(const float* __restrict__ vmean, const float* __restrict__ Wo,
                                const float* __restrict__ bo, float* __restrict__ baseo)
{
    int b = blockIdx.x;
    int col = blockIdx.y * 256 + threadIdx.x;
    float s = bo[col];
    for (int k = 0; k < Dd; k++)
        s += vmean[b * Dd + k] * Wo[(size_t)k * Dd + col];
    baseo[b * Dd + col] = s;
}

// ---------------- broadcast base row into out ---------------------------------
__global__ __launch_bounds__(256) void bcast_out(const float* __restrict__ baseo,
                                                 float* __restrict__ out)
{
    int i = blockIdx.x * 256 + threadIdx.x;            // float4 index into MK
    int b4 = i / (Ll * Dd / 4);
    int c4 = i % (Dd / 4);
    ((float4*)out)[i] = ((const float4*)baseo)[b4 * (Dd / 4) + c4];
}

// ---------------- sparse metric (d-tiled) ------------------------------------
__global__ __launch_bounds__(256) void metric_kernel(const float* __restrict__ Qp,
                                                     const float* __restrict__ Kp,
                                                     const int* __restrict__ sample_idx,
                                                     float* __restrict__ Mout)
{
    int b = blockIdx.z, h = blockIdx.y;
    int l = blockIdx.x * 256 + threadIdx.x;
    __shared__ float Ks[Uu * DK];
    for (int i = threadIdx.x; i < Uu * DK; i += 256) {
        int j = i / DK, d = i % DK;
        int ksl = sample_idx[j];
        Ks[i] = Kp[((size_t)(b * Ll + ksl) * Hh + h) * DK + d];
    }
    __syncthreads();
    const float* qp = &Qp[((size_t)(b * Ll + l) * Hh + h) * DK];
    float acc[Uu];
#pragma unroll
    for (int u = 0; u < Uu; u++) acc[u] = 0.f;
    for (int d0 = 0; d0 < DK; d0 += 8) {
        float4 a0 = *(const float4*)(qp + d0);
        float4 a1 = *(const float4*)(qp + d0 + 4);
#pragma unroll
        for (int u = 0; u < Uu; u++) {
            float4 b0 = *(const float4*)&Ks[u * DK + d0];
            float4 b1 = *(const float4*)&Ks[u * DK + d0 + 4];
            acc[u] += a0.x * b0.x + a0.y * b0.y + a0.z * b0.z + a0.w * b0.w
                    + a1.x * b1.x + a1.y * b1.y + a1.z * b1.z + a1.w * b1.w;
        }
    }
    float mx = -1e30f, sum = 0.f;
#pragma unroll
    for (int u = 0; u < Uu; u++) { mx = fmaxf(mx, acc[u]); sum += acc[u]; }
    Mout[(b * Hh + h) * Ll + l] = mx - sum * (1.0f / Uu);
}

// ---------------- top-45: register-resident + warp shuffles -------------------
__global__ __launch_bounds__(1024) void topk_kernel(const float* __restrict__ Min, int* __restrict__ top)
{
    int bh = blockIdx.x;
    int tid = threadIdx.x;
    int lane = tid & 31, wrp = tid >> 5;
    float4 vv = ((const float4*)(Min + (size_t)bh * Ll))[tid];
    float v[4] = {vv.x, vv.y, vv.z, vv.w};
    __shared__ float swv[32];
    __shared__ int   swi[32];
    __shared__ int   sbwi;

    for (int it = 0; it < Uu; it++) {
        float bv = v[0]; int bj = 0;
#pragma unroll
        for (int j = 1; j < 4; j++) if (v[j] > bv) { bv = v[j]; bj = j; }
        int bi = tid * 4 + bj;
#pragma unroll
        for (int s = 16; s > 0; s >>= 1) {
            float ov = __shfl_down_sync(0xffffffffu, bv, s);
            int   oi = __shfl_down_sync(0xffffffffu, bi, s);
            if (ov > bv || (ov == bv && oi < bi)) { bv = ov; bi = oi; }
        }
        if (lane == 0) { swv[wrp] = bv; swi[wrp] = bi; }
        __syncthreads();
        if (wrp == 0) {
            bv = swv[lane]; bi = swi[lane];
#pragma unroll
            for (int s = 16; s > 0; s >>= 1) {
                float ov = __shfl_down_sync(0xffffffffu, bv, s);
                int   oi = __shfl_down_sync(0xffffffffu, bi, s);
                if (ov > bv || (ov == bv && oi < bi)) { bv = ov; bi = oi; }
            }
            if (lane == 0) { sbwi = bi; top[bh * Uu + it] = bi; }
        }
        __syncthreads();
        int widx = sbwi;
        if ((widx >> 2) == tid) v[widx & 3] = -1e38f;
    }
}

// ---------------- attention pass 1: raw scaled scores -------------------------
__global__ __launch_bounds__(256) void attn_scores(const float* __restrict__ Qp,
                                                   const float* __restrict__ Kp,
                                                   const int* __restrict__ top,
                                                   float* __restrict__ attn)
{
    int kc = blockIdx.x, h = blockIdx.y, b = blockIdx.z;
    int bh = b * Hh + h;
    __shared__ float Qs[Uu * DK];
    for (int i = threadIdx.x; i < Uu * DK; i += 256) {
        int u = i >> 6, d = i & 63;
        int lsel = top[bh * Uu + u];
        Qs[i] = Qp[((size_t)(b * Ll + lsel) * Hh + h) * DK + d];
    }
    __syncthreads();
    int k = kc * 256 + threadIdx.x;
    const float* kp = Kp + ((size_t)(b * Ll + k) * Hh + h) * DK;
    float acc[Uu];
#pragma unroll
    for (int u = 0; u < Uu; u++) acc[u] = 0.f;
    for (int d0 = 0; d0 < DK; d0 += 8) {
        float4 k0 = *(const float4*)(kp + d0);
        float4 k1 = *(const float4*)(kp + d0 + 4);
#pragma unroll
        for (int u = 0; u < Uu; u++) {
            float4 q0 = *(const float4*)&Qs[u * DK + d0];
            float4 q1 = *(const float4*)&Qs[u * DK + d0 + 4];
            acc[u] += k0.x * q0.x + k0.y * q0.y + k0.z * q0.z + k0.w * q0.w
                    + k1.x * q1.x + k1.y * q1.y + k1.z * q1.z + k1.w * q1.w;
        }
    }
    float* ap = attn + (size_t)bh * Uu * Ll + k;
#pragma unroll
    for (int u = 0; u < Uu; u++) ap[(size_t)u * Ll] = acc[u] * SCALE;
}

// ---------------- attention pass 2: softmax in place --------------------------
__global__ __launch_bounds__(256) void attn_softmax(float* __restrict__ attn)
{
    size_t row = blockIdx.x;
    float* ap = attn + row * Ll;
    int tid = threadIdx.x;
    __shared__ float red[256];
    float v[16];
    float mx = -1e30f;
#pragma unroll
    for (int i = 0; i < 16; i++) { v[i] = ap[tid + i * 256]; mx = fmaxf(mx, v[i]); }
    red[tid] = mx; __syncthreads();
    for (int s = 128; s > 0; s >>= 1) { if (tid < s) red[tid] = fmaxf(red[tid], red[tid + s]); __syncthreads(); }
    mx = red[0]; __syncthreads();
    float sum = 0.f;
#pragma unroll
    for (int i = 0; i < 16; i++) { v[i] = expf(v[i] - mx); sum += v[i]; }
    red[tid] = sum; __syncthreads();
    for (int s = 128; s > 0; s >>= 1) { if (tid < s) red[tid] += red[tid + s]; __syncthreads(); }
    float inv = 1.0f / red[0];
#pragma unroll
    for (int i = 0; i < 16; i++) ap[tid + i * 256] = v[i] * inv;
}

// ---------------- attention pass 3: partial AV over 128-key chunks ------------
__global__ __launch_bounds__(256) void attn_av(const float* __restrict__ attn,
                                               const float* __restrict__ Vp,
                                               float* __restrict__ part)
{
    int cz = blockIdx.x, h = blockIdx.y, b = blockIdx.z;
    int bh = b * Hh + h;
    int k0 = cz * 128;
    __shared__ float As[Uu][128];
    for (int i = threadIdx.x; i < Uu * 128; i += 256) {
        int u = i >> 7, k = i & 127;
        As[u][k] = attn[((size_t)(bh * Uu + u)) * Ll + k0 + k];
    }
    __syncthreads();
    int d = threadIdx.x & 63, g = threadIdx.x >> 6;
    float acc[12];
#pragma unroll
    for (int i = 0; i < 12; i++) acc[i] = 0.f;
    for (int k = 0; k < 128; k++) {
        float v = Vp[((size_t)(b * Ll + k0 + k) * Hh + h) * DK + d];
#pragma unroll
        for (int i = 0; i < 12; i++) {
            int u = g + i * 4;
            if (u < Uu) acc[i] += As[u][k] * v;
        }
    }
#pragma unroll
    for (int i = 0; i < 12; i++) {
        int u = g + i * 4;
        if (u < Uu) part[(((size_t)bh * 32 + cz) * Uu + u) * 64 + d] = acc[i];
    }
}

// ---------------- attention pass 4: reduce -> delta vs vmean ------------------
__global__ void attn_delta(const float* __restrict__ part, const float* __restrict__ vmean,
                           float* __restrict__ delta)
{
    int blk = blockIdx.x;                 // 1440
    int bh = blk / Uu, u = blk % Uu;
    int d = threadIdx.x;                  // 64
    float s = 0.f;
    for (int c = 0; c < 32; c++) s += part[(((size_t)bh * 32 + c) * Uu + u) * 64 + d];
    int b = bh >> 3, h = bh & 7;
    delta[((size_t)(bh * Uu + u)) * DK + d] = s - vmean[b * Dd + h * DK + d];
}

// ---------------- correction: out[l] += delta @ Wo[h-block] (atomic) ----------
__global__ __launch_bounds__(256) void attn_correct(const float* __restrict__ delta,
                                                    const int* __restrict__ top,
                                                    const float* __restrict__ Wo,
                                                    float* __restrict__ out)
{
    int blk = blockIdx.x;                 // 1440
    int bh = blk / Uu, u = blk % Uu;
    int b = bh >> 3, h = bh & 7;
    int tid = threadIdx.x;
    __shared__ float dsh[DK];
    if (tid < DK) dsh[tid] = delta[((size_t)(bh * Uu + u)) * DK + tid];
    __syncthreads();
    int l = top[bh * Uu + u];
    float* orow = out + (size_t)(b * Ll + l) * Dd;
    const float* wbase = Wo + (size_t)(h * DK) * Dd;
#pragma unroll
    for (int rep = 0; rep < 2; rep++) {
        int col = tid + rep * 256;
        float acc = 0.f;
#pragma unroll 8
        for (int k = 0; k < DK; k++)
            acc += dsh[k] * wbase[(size_t)k * Dd + col];
        atomicAdd(&orow[col], acc);
    }
}

// ---------------- launch ------------------------------------------------------
extern "C" void kernel_launch(void* const* d_in, const int* in_sizes, int n_in,
                              void* d_out, int out_size)
{
    const float* queries = (const float*)d_in[0];
    const float* keys    = (const float*)d_in[1];
    const float* values  = (const float*)d_in[2];
    const int*   sample  = (const int*)d_in[3];
    const float* Wq = (const float*)d_in[4];  const float* bq = (const float*)d_in[5];
    const float* Wk = (const float*)d_in[6];  const float* bk = (const float*)d_in[7];
    const float* Wv = (const float*)d_in[8];  const float* bv = (const float*)d_in[9];
    const float* Wo = (const float*)d_in[10]; const float* bo = (const float*)d_in[11];

    float* out      = (float*)d_out;
    float* attn_out = out + (size_t)MK;

    __nv_bfloat16 *XH, *XL, *X2, *WtH, *WtL, *Wt2;
    float *P, *M, *vpart, *vmean, *baseo, *part, *delta;
    int *top;
    cudaGetSymbolAddress((void**)&XH, g_XH);
    cudaGetSymbolAddress((void**)&XL, g_XL);
    cudaGetSymbolAddress((void**)&X2, g_X2);
    cudaGetSymbolAddress((void**)&WtH, g_WtH);
    cudaGetSymbolAddress((void**)&WtL, g_WtL);
    cudaGetSymbolAddress((void**)&Wt2, g_Wt2);
    cudaGetSymbolAddress((void**)&P, g_P);
    cudaGetSymbolAddress((void**)&M, g_M);
    cudaGetSymbolAddress((void**)&vpart, g_vpart);
    cudaGetSymbolAddress((void**)&vmean, g_vmean);
    cudaGetSymbolAddress((void**)&baseo, g_base);
    cudaGetSymbolAddress((void**)&top, g_top);
    cudaGetSymbolAddress((void**)&part, g_part);
    cudaGetSymbolAddress((void**)&delta, g_delta);

    cudaFuncSetAttribute(gemm_hmma, cudaFuncAttributeMaxDynamicSharedMemorySize, GEMM_SMEM);

    const float* Qp = P;
    const float* Kp = P + MK;
    const float* Vp = P + 2 * (size_t)MK;

    // 1. split inputs + weights (Q,K,V only; Wo stays fp32)
    conv_split3_all<<<dim3((MK / 4) / 256, 1, 3), 256>>>(queries, keys, values, XH, XL, X2);
    conv_w3_all<<<dim3(16, 16, 3), dim3(32, 8)>>>(Wq, Wk, Wv, WtH, WtL, Wt2);

    // 2. projections: Q,K = 6-term, V = 3-term (K=64 chunks, 3-stage)
    gemm_hmma<<<dim3(128, 4, 3), 256, GEMM_SMEM>>>(XH, XL, X2, WtH, WtL, Wt2, bq, bk, bv, P);

    // 3. V mean + base output row + broadcast into out
    vmean1<<<dim3(Bb, 32), 256>>>(Vp, vpart);
    vmean2<<<Bb, 512>>>(vpart, vmean);
    base_out_kernel<<<dim3(Bb, 2), 256>>>(vmean, Wo, bo, baseo);
    bcast_out<<<(MK / 4) / 256, 256>>>(baseo, out);

    // 4. sparse metric + top-k
    metric_kernel<<<dim3(Ll / 256, Hh, Bb), 256>>>(Qp, Kp, sample, M);
    topk_kernel<<<Bb * Hh, 1024>>>(M, top);

    // 5. attention multi-pass -> delta
    attn_scores<<<dim3(Ll / 256, Hh, Bb), 256>>>(Qp, Kp, top, attn_out);
    attn_softmax<<<Bb * Hh * Uu, 256>>>(attn_out);
    attn_av<<<dim3(32, Hh, Bb), 256>>>(attn_out, Vp, part);
    attn_delta<<<Bb * Hh * Uu, 64>>>(part, vmean, delta);

    // 6. sparse correction into out (replaces full output GEMM)
    attn_correct<<<Bb * Hh * Uu, 256>>>(delta, top, Wo, out);
}

// round 16
// speedup vs baseline: 1.7867x; 1.0877x over previous
#include <cuda_runtime.h>
#include <cuda_bf16.h>
#include <cstdint>
#include <math.h>

#define Bb 4
#define Ll 4096
#define Dd 512
#define Hh 8
#define DK 64
#define Uu 45
#define SCALE 0.125f
#define MM 16384
#define MK 8388608
#define WSZ 262144

// ---------------- PTX helpers (plain-sm_103-legal) ---------------------------
__device__ __forceinline__ uint32_t smem_u32(const void* p) {
    uint32_t a;
    asm("{ .reg .u64 t; cvta.to.shared.u64 t, %1; cvt.u32.u64 %0, t; }" : "=r"(a) : "l"(p));
    return a;
}
#define CP_ASYNC16(dst, src) \
    asm volatile("cp.async.cg.shared.global [%0], [%1], 16;" :: "r"(dst), "l"(src))
#define CP_COMMIT() asm volatile("cp.async.commit_group;" ::: "memory")
#define CP_WAIT1()  asm volatile("cp.async.wait_group 1;" ::: "memory")

__device__ __forceinline__ void ldsm_x4(uint32_t* r, uint32_t addr) {
    asm volatile("ldmatrix.sync.aligned.m8n8.x4.shared.b16 {%0,%1,%2,%3}, [%4];"
        : "=r"(r[0]), "=r"(r[1]), "=r"(r[2]), "=r"(r[3]) : "r"(addr));
}
__device__ __forceinline__ void mma_bf16(float* d, const uint32_t* a, uint32_t b0, uint32_t b1) {
    asm volatile("mma.sync.aligned.m16n8k16.row.col.f32.bf16.bf16.f32 "
        "{%0,%1,%2,%3}, {%4,%5,%6,%7}, {%8,%9}, {%0,%1,%2,%3};"
        : "+f"(d[0]), "+f"(d[1]), "+f"(d[2]), "+f"(d[3])
        : "r"(a[0]), "r"(a[1]), "r"(a[2]), "r"(a[3]), "r"(b0), "r"(b1));
}

// ---------------- scratch ----------------------------------------------------
__device__ __nv_bfloat16 g_XH[3 * MK];
__device__ __nv_bfloat16 g_XL[3 * MK];
__device__ __nv_bfloat16 g_X2[3 * MK];
__device__ __nv_bfloat16 g_WtH[3 * WSZ];
__device__ __nv_bfloat16 g_WtL[3 * WSZ];
__device__ __nv_bfloat16 g_Wt2[3 * WSZ];
__device__ float g_P[3 * MK];              // Qp | Kp | Vp, (B,L,H,dk)
__device__ float g_M[Bb * Hh * Ll];
__device__ float g_vpart[Bb * 32 * Dd];
__device__ float g_vmean[Bb * Dd];
__device__ float g_base[Bb * Dd];
__device__ int   g_top[Bb * Hh * Uu];
__device__ float g_part[32 * 32 * Uu * DK];   // [bh][chunk][u][d]
__device__ float g_delta[Bb * Hh * Uu * DK];  // new_ctx - vmean per selected row

// ---------------- 3-level split, all inputs in one launch --------------------
__global__ __launch_bounds__(256) void conv_split3_all(
    const float* __restrict__ q, const float* __restrict__ k, const float* __restrict__ v,
    __nv_bfloat16* __restrict__ H, __nv_bfloat16* __restrict__ L,
    __nv_bfloat16* __restrict__ X2)
{
    int z = blockIdx.z;
    int i = blockIdx.x * 256 + threadIdx.x;
    const float* src = (z == 0) ? q : (z == 1) ? k : v;
    float4 val = ((const float4*)src)[i];
    size_t o = (size_t)z * (MK / 4) + i;
    float vv[4] = {val.x, val.y, val.z, val.w};
    __nv_bfloat16 hh[4], mm[4], ll[4];
#pragma unroll
    for (int j = 0; j < 4; j++) {
        hh[j] = __float2bfloat16(vv[j]);
        float r1 = vv[j] - __bfloat162float(hh[j]);
        mm[j] = __float2bfloat16(r1);
        ll[j] = __float2bfloat16(r1 - __bfloat162float(mm[j]));
    }
    ((__nv_bfloat162*)H)[2 * o + 0] = __halves2bfloat162(hh[0], hh[1]);
    ((__nv_bfloat162*)H)[2 * o + 1] = __halves2bfloat162(hh[2], hh[3]);
    ((__nv_bfloat162*)L)[2 * o + 0] = __halves2bfloat162(mm[0], mm[1]);
    ((__nv_bfloat162*)L)[2 * o + 1] = __halves2bfloat162(mm[2], mm[3]);
    if (z < 2) {
        ((__nv_bfloat162*)X2)[2 * o + 0] = __halves2bfloat162(ll[0], ll[1]);
        ((__nv_bfloat162*)X2)[2 * o + 1] = __halves2bfloat162(ll[2], ll[3]);
    }
}

// ---------------- weight transpose + 3-level split (Q,K,V only) --------------
__global__ void conv_w3_all(const float* __restrict__ Wq, const float* __restrict__ Wk,
                            const float* __restrict__ Wv,
                            __nv_bfloat16* __restrict__ WtH,
                            __nv_bfloat16* __restrict__ WtL,
                            __nv_bfloat16* __restrict__ Wt2)
{
    __shared__ float t[32][33];
    int z = blockIdx.z;
    const float* W = (z == 0) ? Wq : (z == 1) ? Wk : Wv;
    size_t base = (size_t)z * WSZ;
    int n0 = blockIdx.x * 32, k0 = blockIdx.y * 32;
    int tx = threadIdx.x, ty = threadIdx.y;
#pragma unroll
    for (int i = 0; i < 4; i++)
        t[ty + i * 8][tx] = W[(size_t)(k0 + ty + i * 8) * 512 + n0 + tx];
    __syncthreads();
#pragma unroll
    for (int i = 0; i < 4; i++) {
        int n = n0 + ty + i * 8;
        float v = t[tx][ty + i * 8];
        __nv_bfloat16 hb = __float2bfloat16(v);
        float r1 = v - __bfloat162float(hb);
        __nv_bfloat16 mb = __float2bfloat16(r1);
        WtH[base + (size_t)n * 512 + k0 + tx] = hb;
        WtL[base + (size_t)n * 512 + k0 + tx] = mb;
        Wt2[base + (size_t)n * 512 + k0 + tx] = __float2bfloat16(r1 - __bfloat162float(mb));
    }
}

// ---------------- pairwise HMMA GEMM, K=64 chunks, 3-stage -------------------
__device__ __constant__ int c_tA[6] = {0, 0, 1, 0, 2, 1};
__device__ __constant__ int c_tB[6] = {0, 1, 0, 2, 0, 1};
#define LDAB 72                              // 64 bf16 + 8 pad (144 B rows)
#define STG_BYTES (128 * LDAB * 2)           // 18432 per tile
#define GEMM_SMEM (3 * 2 * STG_BYTES)        // 110592

__global__ __launch_bounds__(256, 2) void gemm_hmma(
    const __nv_bfloat16* __restrict__ A0, const __nv_bfloat16* __restrict__ A1,
    const __nv_bfloat16* __restrict__ A2,
    const __nv_bfloat16* __restrict__ B0, const __nv_bfloat16* __restrict__ B1,
    const __nv_bfloat16* __restrict__ B2,
    const float* __restrict__ bi0, const float* __restrict__ bi1, const float* __restrict__ bi2,
    float* __restrict__ Cout)
{
    extern __shared__ char sm[];
    const int tid = threadIdx.x;
    const int w = tid >> 5, lane = tid & 31;
    const int z = blockIdx.z;
    const int m0 = blockIdx.x * 128, n0 = blockIdx.y * 128;
    const int nt = (z == 2) ? 3 : 6;
    const int NCH = nt * 8;                  // K=64 per chunk

    const __nv_bfloat16* Alev[3] = {A0 + (size_t)z * MK, A1 + (size_t)z * MK, A2 + (size_t)z * MK};
    const __nv_bfloat16* Blev[3] = {B0 + (size_t)z * WSZ, B1 + (size_t)z * WSZ, B2 + (size_t)z * WSZ};

    const int m_off = (w >> 2) * 64, n_off = (w & 3) * 32;
    const int mi = lane >> 3, r8 = lane & 7;

    float acc[4][4][4];
#pragma unroll
    for (int i = 0; i < 4; i++)
#pragma unroll
        for (int j = 0; j < 4; j++)
#pragma unroll
            for (int q = 0; q < 4; q++) acc[i][j][q] = 0.f;

    const uint32_t sbase = smem_u32(sm);
    const int lrow = tid >> 3;               // 0..31 (+32,+64,+96)
    const int lcg  = (tid & 7) * 8;          // bf16 col within 64-wide chunk

    auto load_chunk = [&](int c, int stg) {
        int t = c >> 3, k0 = (c & 7) * 64;
        const __nv_bfloat16* Asrc = Alev[c_tA[t]];
        const __nv_bfloat16* Bsrc = Blev[c_tB[t]];
        uint32_t sA = sbase + stg * (2 * STG_BYTES);
        uint32_t sB = sA + STG_BYTES;
#pragma unroll
        for (int i = 0; i < 4; i++) {
            int row = lrow + i * 32;
            CP_ASYNC16(sA + (row * LDAB + lcg) * 2, Asrc + (size_t)(m0 + row) * 512 + k0 + lcg);
            CP_ASYNC16(sB + (row * LDAB + lcg) * 2, Bsrc + (size_t)(n0 + row) * 512 + k0 + lcg);
        }
    };

    load_chunk(0, 0); CP_COMMIT();
    load_chunk(1, 1); CP_COMMIT();

    int buf = 0, pre = 2;
    for (int c = 0; c < NCH; c++) {
        CP_WAIT1();
        __syncthreads();
        if (c + 2 < NCH) load_chunk(c + 2, pre);
        CP_COMMIT();

        uint32_t sA = sbase + buf * (2 * STG_BYTES);
        uint32_t sB = sA + STG_BYTES;
#pragma unroll
        for (int kk = 0; kk < 4; kk++) {
            uint32_t a[4][4], b[2][4];
#pragma unroll
            for (int i = 0; i < 4; i++)
                ldsm_x4(a[i], sA + (uint32_t)(m_off + i * 16 + ((mi & 1) << 3) + r8) * 144
                              + kk * 32 + ((mi >> 1) << 4));
#pragma unroll
            for (int jg = 0; jg < 2; jg++)
                ldsm_x4(b[jg], sB + (uint32_t)(n_off + jg * 16 + ((mi >> 1) << 3) + r8) * 144
                               + kk * 32 + ((mi & 1) << 4));
#pragma unroll
            for (int i = 0; i < 4; i++)
#pragma unroll
                for (int j = 0; j < 4; j++)
                    mma_bf16(acc[i][j], a[i], b[j >> 1][(j & 1) * 2], b[j >> 1][(j & 1) * 2 + 1]);
        }
        buf = (buf == 2) ? 0 : buf + 1;
        pre = (pre == 2) ? 0 : pre + 1;
    }

    const float* bs = (z == 0) ? bi0 : (z == 1) ? bi1 : bi2;
    float* Cz = Cout + (size_t)z * MK;
#pragma unroll
    for (int i = 0; i < 4; i++) {
        int row0 = m0 + m_off + i * 16 + (lane >> 2);
#pragma unroll
        for (int j = 0; j < 4; j++) {
            int col = n0 + n_off + j * 8 + (lane & 3) * 2;
            float bx = bs[col], by = bs[col + 1];
            float2 v0 = make_float2(acc[i][j][0] + bx, acc[i][j][1] + by);
            float2 v1 = make_float2(acc[i][j][2] + bx, acc[i][j][3] + by);
            *(float2*)(Cz + (size_t)row0 * 512 + col) = v0;
            *(float2*)(Cz + (size_t)(row0 + 8) * 512 + col) = v1;
        }
    }
}

// ---------------- V mean: coalesced two-stage --------------------------------
__global__ __launch_bounds__(256) void vmean1(const float* __restrict__ Vp, float* __restrict__ vpart)
{
    int b = blockIdx.x, c = blockIdx.y;
    int col4 = threadIdx.x & 127;
    int half = threadIdx.x >> 7;
    const float4* base = (const float4*)(Vp + (size_t)(b * Ll + c * 128) * Dd);
    float4 acc = make_float4(0.f, 0.f, 0.f, 0.f);
    for (int r = half; r < 128; r += 2) {
        float4 v = base[(size_t)r * 128 + col4];
        acc.x += v.x; acc.y += v.y; acc.z += v.z; acc.w += v.w;
    }
    __shared__ float4 smv[128];
    if (half == 1) smv[col4] = acc;
    __syncthreads();
    if (half == 0) {
        float4 o = smv[col4];
        o.x += acc.x; o.y += acc.y; o.z += acc.z; o.w += acc.w;
        ((float4*)vpart)[((size_t)(b * 32 + c)) * 128 + col4] = o;
    }
}

__global__ void vmean2(const float* __restrict__ vpart, float* __restrict__ vmean)
{
    int b = blockIdx.x, d = threadIdx.x;
    float s = 0.f;
    for (int c = 0; c < 32; c++) s += vpart[((size_t)(b * 32 + c)) * 512 + d];
    vmean[b * Dd + d] = s * (1.0f / Ll);
}

// ---------------- base output row: vmean @ Wo + bo ----------------------------
__global__ void base_out_kernel(const float* __restrict__ vmean, const float* __restrict__ Wo,
                                const float* __restrict__ bo, float* __restrict__ baseo)
{
    int b = blockIdx.x;
    int col = blockIdx.y * 256 + threadIdx.x;
    float s = bo[col];
    for (int k = 0; k < Dd; k++)
        s += vmean[b * Dd + k] * Wo[(size_t)k * Dd + col];
    baseo[b * Dd + col] = s;
}

// ---------------- broadcast base row into out ---------------------------------
__global__ __launch_bounds__(256) void bcast_out(const float* __restrict__ baseo,
                                                 float* __restrict__ out)
{
    int i = blockIdx.x * 256 + threadIdx.x;            // float4 index into MK
    int b4 = i / (Ll * Dd / 4);
    int c4 = i % (Dd / 4);
    ((float4*)out)[i] = ((const float4*)baseo)[b4 * (Dd / 4) + c4];
}

// ---------------- sparse metric (d-tiled) ------------------------------------
__global__ __launch_bounds__(256) void metric_kernel(const float* __restrict__ Qp,
                                                     const float* __restrict__ Kp,
                                                     const int* __restrict__ sample_idx,
                                                     float* __restrict__ Mout)
{
    int b = blockIdx.z, h = blockIdx.y;
    int l = blockIdx.x * 256 + threadIdx.x;
    __shared__ float Ks[Uu * DK];
    for (int i = threadIdx.x; i < Uu * DK; i += 256) {
        int j = i / DK, d = i % DK;
        int ksl = sample_idx[j];
        Ks[i] = Kp[((size_t)(b * Ll + ksl) * Hh + h) * DK + d];
    }
    __syncthreads();
    const float* qp = &Qp[((size_t)(b * Ll + l) * Hh + h) * DK];
    float acc[Uu];
#pragma unroll
    for (int u = 0; u < Uu; u++) acc[u] = 0.f;
    for (int d0 = 0; d0 < DK; d0 += 8) {
        float4 a0 = *(const float4*)(qp + d0);
        float4 a1 = *(const float4*)(qp + d0 + 4);
#pragma unroll
        for (int u = 0; u < Uu; u++) {
            float4 b0 = *(const float4*)&Ks[u * DK + d0];
            float4 b1 = *(const float4*)&Ks[u * DK + d0 + 4];
            acc[u] += a0.x * b0.x + a0.y * b0.y + a0.z * b0.z + a0.w * b0.w
                    + a1.x * b1.x + a1.y * b1.y + a1.z * b1.z + a1.w * b1.w;
        }
    }
    float mx = -1e30f, sum = 0.f;
#pragma unroll
    for (int u = 0; u < Uu; u++) { mx = fmaxf(mx, acc[u]); sum += acc[u]; }
    Mout[(b * Hh + h) * Ll + l] = mx - sum * (1.0f / Uu);
}

// ---------------- top-45: register-resident + warp shuffles -------------------
__global__ __launch_bounds__(1024) void topk_kernel(const float* __restrict__ Min, int* __restrict__ top)
{
    int bh = blockIdx.x;
    int tid = threadIdx.x;
    int lane = tid & 31, wrp = tid >> 5;
    float4 vv = ((const float4*)(Min + (size_t)bh * Ll))[tid];
    float v[4] = {vv.x, vv.y, vv.z, vv.w};
    __shared__ float swv[32];
    __shared__ int   swi[32];
    __shared__ int   sbwi;

    for (int it = 0; it < Uu; it++) {
        float bv = v[0]; int bj = 0;
#pragma unroll
        for (int j = 1; j < 4; j++) if (v[j] > bv) { bv = v[j]; bj = j; }
        int bi = tid * 4 + bj;
#pragma unroll
        for (int s = 16; s > 0; s >>= 1) {
            float ov = __shfl_down_sync(0xffffffffu, bv, s);
            int   oi = __shfl_down_sync(0xffffffffu, bi, s);
            if (ov > bv || (ov == bv && oi < bi)) { bv = ov; bi = oi; }
        }
        if (lane == 0) { swv[wrp] = bv; swi[wrp] = bi; }
        __syncthreads();
        if (wrp == 0) {
            bv = swv[lane]; bi = swi[lane];
#pragma unroll
            for (int s = 16; s > 0; s >>= 1) {
                float ov = __shfl_down_sync(0xffffffffu, bv, s);
                int   oi = __shfl_down_sync(0xffffffffu, bi, s);
                if (ov > bv || (ov == bv && oi < bi)) { bv = ov; bi = oi; }
            }
            if (lane == 0) { sbwi = bi; top[bh * Uu + it] = bi; }
        }
        __syncthreads();
        int widx = sbwi;
        if ((widx >> 2) == tid) v[widx & 3] = -1e38f;
    }
}

// ---------------- attention pass 1: raw scaled scores -------------------------
__global__ __launch_bounds__(256) void attn_scores(const float* __restrict__ Qp,
                                                   const float* __restrict__ Kp,
                                                   const int* __restrict__ top,
                                                   float* __restrict__ attn)
{
    int kc = blockIdx.x, h = blockIdx.y, b = blockIdx.z;
    int bh = b * Hh + h;
    __shared__ float Qs[Uu * DK];
    for (int i = threadIdx.x; i < Uu * DK; i += 256) {
        int u = i >> 6, d = i & 63;
        int lsel = top[bh * Uu + u];
        Qs[i] = Qp[((size_t)(b * Ll + lsel) * Hh + h) * DK + d];
    }
    __syncthreads();
    int k = kc * 256 + threadIdx.x;
    const float* kp = Kp + ((size_t)(b * Ll + k) * Hh + h) * DK;
    float acc[Uu];
#pragma unroll
    for (int u = 0; u < Uu; u++) acc[u] = 0.f;
    for (int d0 = 0; d0 < DK; d0 += 8) {
        float4 k0 = *(const float4*)(kp + d0);
        float4 k1 = *(const float4*)(kp + d0 + 4);
#pragma unroll
        for (int u = 0; u < Uu; u++) {
            float4 q0 = *(const float4*)&Qs[u * DK + d0];
            float4 q1 = *(const float4*)&Qs[u * DK + d0 + 4];
            acc[u] += k0.x * q0.x + k0.y * q0.y + k0.z * q0.z + k0.w * q0.w
                    + k1.x * q1.x + k1.y * q1.y + k1.z * q1.z + k1.w * q1.w;
        }
    }
    float* ap = attn + (size_t)bh * Uu * Ll + k;
#pragma unroll
    for (int u = 0; u < Uu; u++) ap[(size_t)u * Ll] = acc[u] * SCALE;
}

// ---------------- attention pass 2: softmax in place --------------------------
__global__ __launch_bounds__(256) void attn_softmax(float* __restrict__ attn)
{
    size_t row = blockIdx.x;
    float* ap = attn + row * Ll;
    int tid = threadIdx.x;
    __shared__ float red[256];
    float v[16];
    float mx = -1e30f;
#pragma unroll
    for (int i = 0; i < 16; i++) { v[i] = ap[tid + i * 256]; mx = fmaxf(mx, v[i]); }
    red[tid] = mx; __syncthreads();
    for (int s = 128; s > 0; s >>= 1) { if (tid < s) red[tid] = fmaxf(red[tid], red[tid + s]); __syncthreads(); }
    mx = red[0]; __syncthreads();
    float sum = 0.f;
#pragma unroll
    for (int i = 0; i < 16; i++) { v[i] = expf(v[i] - mx); sum += v[i]; }
    red[tid] = sum; __syncthreads();
    for (int s = 128; s > 0; s >>= 1) { if (tid < s) red[tid] += red[tid + s]; __syncthreads(); }
    float inv = 1.0f / red[0];
#pragma unroll
    for (int i = 0; i < 16; i++) ap[tid + i * 256] = v[i] * inv;
}

// ---------------- attention pass 3: partial AV over 128-key chunks ------------
__global__ __launch_bounds__(256) void attn_av(const float* __restrict__ attn,
                                               const float* __restrict__ Vp,
                                               float* __restrict__ part)
{
    int cz = blockIdx.x, h = blockIdx.y, b = blockIdx.z;
    int bh = b * Hh + h;
    int k0 = cz * 128;
    __shared__ float As[Uu][128];
    for (int i = threadIdx.x; i < Uu * 128; i += 256) {
        int u = i >> 7, k = i & 127;
        As[u][k] = attn[((size_t)(bh * Uu + u)) * Ll + k0 + k];
    }
    __syncthreads();
    int d = threadIdx.x & 63, g = threadIdx.x >> 6;
    float acc[12];
#pragma unroll
    for (int i = 0; i < 12; i++) acc[i] = 0.f;
    for (int k = 0; k < 128; k++) {
        float v = Vp[((size_t)(b * Ll + k0 + k) * Hh + h) * DK + d];
#pragma unroll
        for (int i = 0; i < 12; i++) {
            int u = g + i * 4;
            if (u < Uu) acc[i] += As[u][k] * v;
        }
    }
#pragma unroll
    for (int i = 0; i < 12; i++) {
        int u = g + i * 4;
        if (u < Uu) part[(((size_t)bh * 32 + cz) * Uu + u) * 64 + d] = acc[i];
    }
}

// ---------------- attention pass 4: reduce -> delta vs vmean ------------------
__global__ void attn_delta(const float* __restrict__ part, const float* __restrict__ vmean,
                           float* __restrict__ delta)
{
    int blk = blockIdx.x;                 // 1440
    int bh = blk / Uu, u = blk % Uu;
    int d = threadIdx.x;                  // 64
    float s = 0.f;
    for (int c = 0; c < 32; c++) s += part[(((size_t)bh * 32 + c) * Uu + u) * 64 + d];
    int b = bh >> 3, h = bh & 7;
    delta[((size_t)(bh * Uu + u)) * DK + d] = s - vmean[b * Dd + h * DK + d];
}

// ---------------- correction: out[l] += delta @ Wo[h-block] (atomic) ----------
__global__ __launch_bounds__(256) void attn_correct(const float* __restrict__ delta,
                                                    const int* __restrict__ top,
                                                    const float* __restrict__ Wo,
                                                    float* __restrict__ out)
{
    int blk = blockIdx.x;                 // 1440
    int bh = blk / Uu, u = blk % Uu;
    int b = bh >> 3, h = bh & 7;
    int tid = threadIdx.x;
    __shared__ float dsh[DK];
    if (tid < DK) dsh[tid] = delta[((size_t)(bh * Uu + u)) * DK + tid];
    __syncthreads();
    int l = top[bh * Uu + u];
    float* orow = out + (size_t)(b * Ll + l) * Dd;
    const float* wbase = Wo + (size_t)(h * DK) * Dd;
#pragma unroll
    for (int rep = 0; rep < 2; rep++) {
        int col = tid + rep * 256;
        float acc = 0.f;
#pragma unroll 8
        for (int k = 0; k < DK; k++)
            acc += dsh[k] * wbase[(size_t)k * Dd + col];
        atomicAdd(&orow[col], acc);
    }
}

// ---------------- stream/event objects (created once, first call is uncaptured)
static cudaStream_t g_s1;
static cudaEvent_t g_ev0, g_evW, g_evG, g_ev1;
static bool g_init = false;

// ---------------- launch ------------------------------------------------------
extern "C" void kernel_launch(void* const* d_in, const int* in_sizes, int n_in,
                              void* d_out, int out_size)
{
    const float* queries = (const float*)d_in[0];
    const float* keys    = (const float*)d_in[1];
    const float* values  = (const float*)d_in[2];
    const int*   sample  = (const int*)d_in[3];
    const float* Wq = (const float*)d_in[4];  const float* bq = (const float*)d_in[5];
    const float* Wk = (const float*)d_in[6];  const float* bk = (const float*)d_in[7];
    const float* Wv = (const float*)d_in[8];  const float* bv = (const float*)d_in[9];
    const float* Wo = (const float*)d_in[10]; const float* bo = (const float*)d_in[11];

    float* out      = (float*)d_out;
    float* attn_out = out + (size_t)MK;

    __nv_bfloat16 *XH, *XL, *X2, *WtH, *WtL, *Wt2;
    float *P, *M, *vpart, *vmean, *baseo, *part, *delta;
    int *top;
    cudaGetSymbolAddress((void**)&XH, g_XH);
    cudaGetSymbolAddress((void**)&XL, g_XL);
    cudaGetSymbolAddress((void**)&X2, g_X2);
    cudaGetSymbolAddress((void**)&WtH, g_WtH);
    cudaGetSymbolAddress((void**)&WtL, g_WtL);
    cudaGetSymbolAddress((void**)&Wt2, g_Wt2);
    cudaGetSymbolAddress((void**)&P, g_P);
    cudaGetSymbolAddress((void**)&M, g_M);
    cudaGetSymbolAddress((void**)&vpart, g_vpart);
    cudaGetSymbolAddress((void**)&vmean, g_vmean);
    cudaGetSymbolAddress((void**)&baseo, g_base);
    cudaGetSymbolAddress((void**)&top, g_top);
    cudaGetSymbolAddress((void**)&part, g_part);
    cudaGetSymbolAddress((void**)&delta, g_delta);

    cudaFuncSetAttribute(gemm_hmma, cudaFuncAttributeMaxDynamicSharedMemorySize, GEMM_SMEM);

    if (!g_init) {
        cudaStreamCreateWithFlags(&g_s1, cudaStreamNonBlocking);
        cudaEventCreateWithFlags(&g_ev0, cudaEventDisableTiming);
        cudaEventCreateWithFlags(&g_evW, cudaEventDisableTiming);
        cudaEventCreateWithFlags(&g_evG, cudaEventDisableTiming);
        cudaEventCreateWithFlags(&g_ev1, cudaEventDisableTiming);
        g_init = true;
    }

    const float* Qp = P;
    const float* Kp = P + MK;
    const float* Vp = P + 2 * (size_t)MK;

    // fork: weight split on s1, input split on default stream
    cudaEventRecord(g_ev0, 0);
    cudaStreamWaitEvent(g_s1, g_ev0, 0);
    conv_w3_all<<<dim3(16, 16, 3), dim3(32, 8), 0, g_s1>>>(Wq, Wk, Wv, WtH, WtL, Wt2);
    cudaEventRecord(g_evW, g_s1);

    conv_split3_all<<<dim3((MK / 4) / 256, 1, 3), 256>>>(queries, keys, values, XH, XL, X2);
    cudaStreamWaitEvent(0, g_evW, 0);

    // projections: Q,K = 6-term, V = 3-term (K=64 chunks, 3-stage)
    gemm_hmma<<<dim3(128, 4, 3), 256, GEMM_SMEM>>>(XH, XL, X2, WtH, WtL, Wt2, bq, bk, bv, P);
    cudaEventRecord(g_evG, 0);

    // side stream: V-mean chain + base output broadcast (independent of metric path)
    cudaStreamWaitEvent(g_s1, g_evG, 0);
    vmean1<<<dim3(Bb, 32), 256, 0, g_s1>>>(Vp, vpart);
    vmean2<<<Bb, 512, 0, g_s1>>>(vpart, vmean);
    base_out_kernel<<<dim3(Bb, 2), 256, 0, g_s1>>>(vmean, Wo, bo, baseo);
    bcast_out<<<(MK / 4) / 256, 256, 0, g_s1>>>(baseo, out);
    cudaEventRecord(g_ev1, g_s1);

    // main stream: selection + attention
    metric_kernel<<<dim3(Ll / 256, Hh, Bb), 256>>>(Qp, Kp, sample, M);
    topk_kernel<<<Bb * Hh, 1024>>>(M, top);
    attn_scores<<<dim3(Ll / 256, Hh, Bb), 256>>>(Qp, Kp, top, attn_out);
    attn_softmax<<<Bb * Hh * Uu, 256>>>(attn_out);
    attn_av<<<dim3(32, Hh, Bb), 256>>>(attn_out, Vp, part);

    // join: delta needs vmean, correct needs bcast'd out
    cudaStreamWaitEvent(0, g_ev1, 0);
    attn_delta<<<Bb * Hh * Uu, 64>>>(part, vmean, delta);
    attn_correct<<<Bb * Hh * Uu, 256>>>(delta, top, Wo, out);
}